// round 1
// baseline (speedup 1.0000x reference)
#include <cuda_runtime.h>
#include <math.h>
#include <stdint.h>

// Problem constants
#define BQ 4
#define HH 64
#define WW 64
#define CC 128
#define DI 256
#define NS 16
#define RR 8
#define KD 4          // scan directions
#define LL 4096       // H*W
#define BL (BQ*LL)    // 16384 pixel-rows
#define CS 128        // scan chunk size
#define NCH (LL/CS)   // 32 chunks

// -------------------- device scratch (static, no allocs) --------------------
__device__ float g_x1[BL*DI];        // x_ (conv input)
__device__ float g_sz[BL*DI];        // silu(z)
__device__ float g_xc[BL*DI];        // conv+silu output, [b*L+p][d]
__device__ float g_xd[BL*160];       // x_proj output per pixel: [b*L+p][k*40+c]
__device__ float g_y [BL*DI];        // scan merged output (atomic accum)
__device__ float g_yn[BL*DI];        // onorm(y) * silu(z)
__device__ float g_xmid[BL*CC];      // after out_proj + residual
__device__ float g_hbuf[BL*4*CC];    // MLP hidden
__device__ float g_P[16*NCH*NS*DI];  // chunk decay products
__device__ float g_S[16*NCH*NS*DI];  // chunk local states -> incoming states
__device__ float2 g_st1[BL];
__device__ float2 g_st2[BL];

// -------------------- small math helpers --------------------
__device__ __forceinline__ float silu_f(float x){ return x / (1.f + __expf(-x)); }
__device__ __forceinline__ float softplus_f(float x){
    return fmaxf(x, 0.f) + __logf(1.f + __expf(-fabsf(x)));
}
__device__ __forceinline__ float gelu_f(float x){
    return 0.5f * x * (1.f + erff(x * 0.70710678118654752f));
}
// pixel index read/written by scan direction k at global step T
__device__ __forceinline__ int pmap(int k, int T){
    int t = (k & 2) ? (LL - 1 - T) : T;
    return (k & 1) ? ((t & 63) * 64 + (t >> 6)) : t;
}

// -------------------- LN row stats --------------------
template<int D>
__global__ void ln_stats(const float* __restrict__ x, float2* __restrict__ st){
    int row = blockIdx.x;
    float v = x[(size_t)row * D + threadIdx.x];
    float s1 = v, s2 = v * v;
    #pragma unroll
    for (int o = 16; o; o >>= 1){
        s1 += __shfl_xor_sync(0xffffffffu, s1, o);
        s2 += __shfl_xor_sync(0xffffffffu, s2, o);
    }
    __shared__ float r1[D/32], r2[D/32];
    int w = threadIdx.x >> 5;
    if ((threadIdx.x & 31) == 0){ r1[w] = s1; r2[w] = s2; }
    __syncthreads();
    if (threadIdx.x == 0){
        float a = 0.f, b = 0.f;
        #pragma unroll
        for (int i = 0; i < D/32; i++){ a += r1[i]; b += r2[i]; }
        float mu = a / D;
        float var = b / D - mu * mu;
        st[row] = make_float2(mu, rsqrtf(var + 1e-5f));
    }
}

// -------------------- generic fp32 GEMM with fused epilogues --------------------
// C[M,N] = op(A)[M,K] * B[K,N]
// NORMA: A element -> (a-mu)*rstd*nw[k]+nb[k]
// BT:    B element (k,n) = Bm[n*K + k]  (x_proj weights)
// EPI: 0 plain | 1 split (n<256 -> Cmat raw, else out2 = silu) | 2 bias+gelu | 3 (bias?)+residual
template<bool NORMA, bool BT, int EPI>
__global__ void __launch_bounds__(256) gemm_k(
    const float* __restrict__ A, const float* __restrict__ Bm, float* __restrict__ Cmat,
    int M, int Nn, int Kk,
    const float2* __restrict__ stats, const float* __restrict__ nw, const float* __restrict__ nb,
    const float* __restrict__ bias, const float* __restrict__ res, float* __restrict__ out2)
{
    const int GBM = 128, GBN = 64, GBK = 16;
    __shared__ float As[GBK][GBM];
    __shared__ float Bs[GBK][GBN];
    int tid = threadIdx.x;
    int tx = tid & 15, ty = tid >> 4;
    int bm = blockIdx.y * GBM;
    int bn = blockIdx.x * GBN;

    float acc[8][4];
    #pragma unroll
    for (int i = 0; i < 8; i++)
        #pragma unroll
        for (int j = 0; j < 4; j++) acc[i][j] = 0.f;

    for (int kt = 0; kt < Kk; kt += GBK){
        // ---- load A tile (128x16) as float4, optional LN on load ----
        #pragma unroll
        for (int q = 0; q < 2; q++){
            int idx = tid + q * 256;          // 0..511
            int row = idx >> 2;               // 0..127
            int c4  = idx & 3;                // 0..3
            float4 v = *reinterpret_cast<const float4*>(
                &A[(size_t)(bm + row) * Kk + kt + c4 * 4]);
            float vv[4] = {v.x, v.y, v.z, v.w};
            if (NORMA){
                float2 stv = stats[bm + row];
                #pragma unroll
                for (int e = 0; e < 4; e++){
                    int kg = kt + c4 * 4 + e;
                    vv[e] = (vv[e] - stv.x) * stv.y * nw[kg] + nb[kg];
                }
            }
            #pragma unroll
            for (int e = 0; e < 4; e++) As[c4 * 4 + e][row] = vv[e];
        }
        // ---- load B tile (16x64) ----
        if (!BT){
            int row = tid >> 4;               // 0..15
            int c4  = tid & 15;               // 0..15
            int ncol = bn + c4 * 4;
            float x0 = 0.f, x1 = 0.f, x2 = 0.f, x3 = 0.f;
            if (ncol + 3 < Nn){
                float4 v = *reinterpret_cast<const float4*>(
                    &Bm[(size_t)(kt + row) * Nn + ncol]);
                x0 = v.x; x1 = v.y; x2 = v.z; x3 = v.w;
            } else {
                const float* bp = &Bm[(size_t)(kt + row) * Nn];
                if (ncol + 0 < Nn) x0 = bp[ncol + 0];
                if (ncol + 1 < Nn) x1 = bp[ncol + 1];
                if (ncol + 2 < Nn) x2 = bp[ncol + 2];
                if (ncol + 3 < Nn) x3 = bp[ncol + 3];
            }
            Bs[row][c4*4+0] = x0; Bs[row][c4*4+1] = x1;
            Bs[row][c4*4+2] = x2; Bs[row][c4*4+3] = x3;
        } else {
            #pragma unroll
            for (int q = 0; q < 4; q++){
                int idx = tid + q * 256;      // 0..1023
                int kl = idx & 15;
                int nl = idx >> 4;            // 0..63
                float v = 0.f;
                if (bn + nl < Nn) v = Bm[(size_t)(bn + nl) * Kk + kt + kl];
                Bs[kl][nl] = v;
            }
        }
        __syncthreads();
        #pragma unroll
        for (int kk = 0; kk < GBK; kk++){
            float am[8], bb[4];
            #pragma unroll
            for (int i = 0; i < 8; i++) am[i] = As[kk][ty * 8 + i];
            #pragma unroll
            for (int j = 0; j < 4; j++) bb[j] = Bs[kk][tx * 4 + j];
            #pragma unroll
            for (int i = 0; i < 8; i++)
                #pragma unroll
                for (int j = 0; j < 4; j++)
                    acc[i][j] = fmaf(am[i], bb[j], acc[i][j]);
        }
        __syncthreads();
    }
    // ---- epilogue ----
    #pragma unroll
    for (int i = 0; i < 8; i++){
        int r = bm + ty * 8 + i;
        #pragma unroll
        for (int j = 0; j < 4; j++){
            int ncol = bn + tx * 4 + j;
            if (ncol >= Nn) continue;
            float v = acc[i][j];
            if (EPI == 1){
                if (ncol < 256) Cmat[(size_t)r * 256 + ncol] = v;
                else            out2[(size_t)r * 256 + (ncol - 256)] = silu_f(v);
            } else if (EPI == 2){
                v += bias[ncol];
                Cmat[(size_t)r * Nn + ncol] = gelu_f(v);
            } else if (EPI == 3){
                if (bias) v += bias[ncol];
                v += res[(size_t)r * Nn + ncol];
                Cmat[(size_t)r * Nn + ncol] = v;
            } else {
                Cmat[(size_t)r * Nn + ncol] = v;
            }
        }
    }
}

// -------------------- depthwise 3x3 conv + bias + SiLU --------------------
__global__ void conv_dw(const float* __restrict__ wc, const float* __restrict__ bc){
    int pix = blockIdx.x;              // b*L + h*W + w
    int d = threadIdx.x;
    int b = pix >> 12;
    int l = pix & (LL - 1);
    int h = l >> 6;
    int w = l & 63;
    float acc = bc[d];
    #pragma unroll
    for (int dy = -1; dy <= 1; dy++){
        int hh = h + dy;
        if (hh < 0 || hh >= HH) continue;
        #pragma unroll
        for (int dx = -1; dx <= 1; dx++){
            int w2 = w + dx;
            if (w2 < 0 || w2 >= WW) continue;
            acc = fmaf(wc[d * 9 + (dy + 1) * 3 + (dx + 1)],
                       g_x1[((size_t)(b * LL + hh * WW + w2)) * DI + d], acc);
        }
    }
    g_xc[(size_t)pix * DI + d] = silu_f(acc);
}

__global__ void zero_y(){
    size_t i = (size_t)blockIdx.x * 256 + threadIdx.x;
    g_y[i] = 0.f;
}

// -------------------- selective scan: pass 1 (chunk-local) --------------------
__global__ void __launch_bounds__(256) scan_pass1(
    const float* __restrict__ dtw, const float* __restrict__ dtb,
    const float* __restrict__ alog)
{
    int bk = blockIdx.x;               // b*4 + k
    int chunk = blockIdx.y;
    int b = bk >> 2, k = bk & 3;
    int d = threadIdx.x;
    __shared__ float tile[CS * 40];
    int T0 = chunk * CS;
    for (int i = d; i < CS * 40; i += 256){
        int t = i / 40, c = i - t * 40;
        int p = pmap(k, T0 + t);
        tile[i] = g_xd[(size_t)(b * LL + p) * 160 + k * 40 + c];
    }
    __syncthreads();

    float dw[RR];
    #pragma unroll
    for (int r = 0; r < RR; r++) dw[r] = dtw[(size_t)(k * DI + d) * RR + r];
    float db = dtb[k * DI + d];
    float Av[NS];
    #pragma unroll
    for (int n = 0; n < NS; n++) Av[n] = -__expf(alog[(size_t)(k * DI + d) * NS + n]);
    float A0 = Av[0];
    bool fast = true;
    #pragma unroll
    for (int n = 0; n < NS; n++){
        float e = Av[n] - (float)(n + 1) * A0;
        if (fabsf(e) > 1e-5f * fabsf(Av[n]) + 1e-12f) fast = false;
    }
    float S[NS];
    #pragma unroll
    for (int n = 0; n < NS; n++) S[n] = 0.f;
    float dsum = 0.f;

    for (int t = 0; t < CS; t++){
        int p = pmap(k, T0 + t);
        float xt = g_xc[(size_t)(b * LL + p) * DI + d];
        const float* tr = &tile[t * 40];
        float dp = db;
        #pragma unroll
        for (int r = 0; r < RR; r++) dp = fmaf(dw[r], tr[r], dp);
        float delta = softplus_f(dp);
        dsum += delta;
        float du = delta * xt;
        if (fast){
            float g = __expf(delta * A0);
            float a = g;
            #pragma unroll
            for (int n = 0; n < NS; n++){
                S[n] = fmaf(a, S[n], du * tr[8 + n]);
                a *= g;
            }
        } else {
            #pragma unroll
            for (int n = 0; n < NS; n++){
                float a = __expf(delta * Av[n]);
                S[n] = fmaf(a, S[n], du * tr[8 + n]);
            }
        }
    }
    size_t base = ((size_t)(bk * NCH + chunk) * NS) * DI + d;
    #pragma unroll
    for (int n = 0; n < NS; n++){
        g_P[base + (size_t)n * DI] = __expf(dsum * Av[n]); // prod_t exp(delta_t*A[n])
        g_S[base + (size_t)n * DI] = S[n];
    }
}

// -------------------- scan pass 2: carry across chunks --------------------
__global__ void scan_pass2(){
    int id = blockIdx.x * 256 + threadIdx.x;   // 16*16*256 = 65536
    int d  = id & 255;
    int n  = (id >> 8) & 15;
    int bk = id >> 12;
    float Hc = 0.f;
    size_t stride = (size_t)NS * DI;
    size_t base = ((size_t)bk * NCH * NS + n) * DI + d;
    for (int c = 0; c < NCH; c++){
        size_t a = base + (size_t)c * stride;
        float Pv = g_P[a];
        float Sv = g_S[a];
        g_S[a] = Hc;                 // incoming state for chunk c
        Hc = fmaf(Pv, Hc, Sv);
    }
}

// -------------------- scan pass 3: replay + y + merge (atomic) --------------------
__global__ void __launch_bounds__(256) scan_pass3(
    const float* __restrict__ dtw, const float* __restrict__ dtb,
    const float* __restrict__ alog, const float* __restrict__ Dsv)
{
    int bk = blockIdx.x;
    int chunk = blockIdx.y;
    int b = bk >> 2, k = bk & 3;
    int d = threadIdx.x;
    __shared__ float tile[CS * 40];
    int T0 = chunk * CS;
    for (int i = d; i < CS * 40; i += 256){
        int t = i / 40, c = i - t * 40;
        int p = pmap(k, T0 + t);
        tile[i] = g_xd[(size_t)(b * LL + p) * 160 + k * 40 + c];
    }
    __syncthreads();

    float dw[RR];
    #pragma unroll
    for (int r = 0; r < RR; r++) dw[r] = dtw[(size_t)(k * DI + d) * RR + r];
    float db = dtb[k * DI + d];
    float Dk = Dsv[k * DI + d];
    float Av[NS];
    #pragma unroll
    for (int n = 0; n < NS; n++) Av[n] = -__expf(alog[(size_t)(k * DI + d) * NS + n]);
    float A0 = Av[0];
    bool fast = true;
    #pragma unroll
    for (int n = 0; n < NS; n++){
        float e = Av[n] - (float)(n + 1) * A0;
        if (fabsf(e) > 1e-5f * fabsf(Av[n]) + 1e-12f) fast = false;
    }
    float h[NS];
    size_t base = ((size_t)(bk * NCH + chunk) * NS) * DI + d;
    #pragma unroll
    for (int n = 0; n < NS; n++) h[n] = g_S[base + (size_t)n * DI];

    for (int t = 0; t < CS; t++){
        int p = pmap(k, T0 + t);
        size_t pidx = (size_t)(b * LL + p) * DI + d;
        float xt = g_xc[pidx];
        const float* tr = &tile[t * 40];
        float dp = db;
        #pragma unroll
        for (int r = 0; r < RR; r++) dp = fmaf(dw[r], tr[r], dp);
        float delta = softplus_f(dp);
        float du = delta * xt;
        float y = 0.f;
        if (fast){
            float g = __expf(delta * A0);
            float a = g;
            #pragma unroll
            for (int n = 0; n < NS; n++){
                h[n] = fmaf(a, h[n], du * tr[8 + n]);
                y = fmaf(h[n], tr[24 + n], y);
                a *= g;
            }
        } else {
            #pragma unroll
            for (int n = 0; n < NS; n++){
                float a = __expf(delta * Av[n]);
                h[n] = fmaf(a, h[n], du * tr[8 + n]);
                y = fmaf(h[n], tr[24 + n], y);
            }
        }
        y = fmaf(Dk, xt, y);
        atomicAdd(&g_y[pidx], y);
    }
}

// -------------------- out-norm (LN over DI) * silu(z) --------------------
__global__ void onorm_mul(const float* __restrict__ onw, const float* __restrict__ onb){
    int row = blockIdx.x;
    int d = threadIdx.x;  // 256
    float v = g_y[(size_t)row * DI + d];
    float s1 = v, s2 = v * v;
    #pragma unroll
    for (int o = 16; o; o >>= 1){
        s1 += __shfl_xor_sync(0xffffffffu, s1, o);
        s2 += __shfl_xor_sync(0xffffffffu, s2, o);
    }
    __shared__ float r1[8], r2[8];
    int w = d >> 5;
    if ((d & 31) == 0){ r1[w] = s1; r2[w] = s2; }
    __syncthreads();
    float a = 0.f, bsum = 0.f;
    #pragma unroll
    for (int i = 0; i < 8; i++){ a += r1[i]; bsum += r2[i]; }
    float mu = a / DI;
    float var = bsum / DI - mu * mu;
    float rs = rsqrtf(var + 1e-5f);
    float o = (v - mu) * rs * onw[d] + onb[d];
    g_yn[(size_t)row * DI + d] = o * g_sz[(size_t)row * DI + d];
}

// -------------------- host launch --------------------
extern "C" void kernel_launch(void* const* d_in, const int* in_sizes, int n_in,
                              void* d_out, int out_size)
{
    (void)in_sizes; (void)n_in; (void)out_size;
    const float* input     = (const float*)d_in[0];
    const float* ln1_w     = (const float*)d_in[1];
    const float* ln1_b     = (const float*)d_in[2];
    const float* in_proj_w = (const float*)d_in[3];
    const float* conv_w    = (const float*)d_in[4];
    const float* conv_b    = (const float*)d_in[5];
    const float* x_proj_w  = (const float*)d_in[6];
    const float* dt_w      = (const float*)d_in[7];
    const float* dt_b      = (const float*)d_in[8];
    const float* A_log     = (const float*)d_in[9];
    const float* Ds        = (const float*)d_in[10];
    const float* onorm_w   = (const float*)d_in[11];
    const float* onorm_b   = (const float*)d_in[12];
    const float* out_proj_w= (const float*)d_in[13];
    const float* ln2_w     = (const float*)d_in[14];
    const float* ln2_b     = (const float*)d_in[15];
    const float* fc1_w     = (const float*)d_in[16];
    const float* fc1_b     = (const float*)d_in[17];
    const float* fc2_w     = (const float*)d_in[18];
    const float* fc2_b     = (const float*)d_in[19];

    float *px1, *psz, *pxc, *pxd, *pyn, *pxmid, *ph;
    float2 *pst1, *pst2;
    cudaGetSymbolAddress((void**)&px1,  g_x1);
    cudaGetSymbolAddress((void**)&psz,  g_sz);
    cudaGetSymbolAddress((void**)&pxc,  g_xc);
    cudaGetSymbolAddress((void**)&pxd,  g_xd);
    cudaGetSymbolAddress((void**)&pyn,  g_yn);
    cudaGetSymbolAddress((void**)&pxmid,g_xmid);
    cudaGetSymbolAddress((void**)&ph,   g_hbuf);
    cudaGetSymbolAddress((void**)&pst1, g_st1);
    cudaGetSymbolAddress((void**)&pst2, g_st2);

    // 1. LN1 stats + (LN1 -> in_proj) GEMM, split x_/silu(z)
    ln_stats<128><<<BL, 128>>>(input, pst1);
    gemm_k<true, false, 1><<<dim3(8, 128), 256>>>(
        input, in_proj_w, px1, BL, 512, 128, pst1, ln1_w, ln1_b,
        nullptr, nullptr, psz);

    // 2. depthwise conv + bias + SiLU
    conv_dw<<<BL, 256>>>(conv_w, conv_b);

    // 3. x_proj (all 4 directions stacked): [BL,256]@[256,160]
    gemm_k<false, true, 0><<<dim3(3, 128), 256>>>(
        pxc, x_proj_w, pxd, BL, 160, 256, nullptr, nullptr, nullptr,
        nullptr, nullptr, nullptr);

    // 4. selective scan (chunked) + merge
    zero_y<<<(BL * DI) / 256, 256>>>();
    scan_pass1<<<dim3(16, NCH), 256>>>(dt_w, dt_b, A_log);
    scan_pass2<<<256, 256>>>();
    scan_pass3<<<dim3(16, NCH), 256>>>(dt_w, dt_b, A_log, Ds);

    // 5. out-norm * silu(z), then out_proj + residual(input)
    onorm_mul<<<BL, 256>>>(onorm_w, onorm_b);
    gemm_k<false, false, 3><<<dim3(2, 128), 256>>>(
        pyn, out_proj_w, pxmid, BL, 128, 256, nullptr, nullptr, nullptr,
        nullptr, input, nullptr);

    // 6. MLP: LN2 -> fc1+GELU -> fc2 + residual
    ln_stats<128><<<BL, 128>>>(pxmid, pst2);
    gemm_k<true, false, 2><<<dim3(8, 128), 256>>>(
        pxmid, fc1_w, ph, BL, 512, 128, pst2, ln2_w, ln2_b,
        fc1_b, nullptr, nullptr);
    gemm_k<false, false, 3><<<dim3(2, 128), 256>>>(
        ph, fc2_w, (float*)d_out, BL, 128, 512, nullptr, nullptr, nullptr,
        fc2_b, pxmid, nullptr);
}

// round 2
// speedup vs baseline: 1.3716x; 1.3716x over previous
#include <cuda_runtime.h>
#include <math.h>
#include <stdint.h>

// Problem constants
#define BQ 4
#define HH 64
#define WW 64
#define CC 128
#define DI 256
#define NS 16
#define RR 8
#define LL 4096       // H*W
#define BL (BQ*LL)    // 16384 pixel-rows
#define CS 128        // scan chunk size
#define NCH (LL/CS)   // 32 chunks

// -------------------- device scratch (static, no allocs) --------------------
__device__ __align__(16) float g_x1[BL*DI];        // x_ (conv input)
__device__ __align__(16) float g_sz[BL*DI];        // silu(z)
__device__ __align__(16) float g_xc[BL*DI];        // conv+silu output
__device__ __align__(16) float g_xd[BL*160];       // x_proj output per pixel
__device__ __align__(16) float g_y [BL*DI];        // scan merged output (atomic accum)
__device__ __align__(16) float g_yn[BL*DI];        // onorm(y) * silu(z)
__device__ __align__(16) float g_xmid[BL*CC];      // after out_proj + residual
__device__ __align__(16) float g_hbuf[BL*4*CC];    // MLP hidden
__device__ __align__(16) float g_P[16*NCH*NS*DI];  // chunk decay products
__device__ __align__(16) float g_S[16*NCH*NS*DI];  // chunk states
__device__ float2 g_st1[BL];
__device__ float2 g_st2[BL];

// -------------------- small math helpers --------------------
__device__ __forceinline__ float silu_f(float x){ return x / (1.f + __expf(-x)); }
__device__ __forceinline__ float softplus_f(float x){
    return fmaxf(x, 0.f) + __logf(1.f + __expf(-fabsf(x)));
}
__device__ __forceinline__ float gelu_f(float x){
    return 0.5f * x * (1.f + erff(x * 0.70710678118654752f));
}
__device__ __forceinline__ uint32_t f2tf32(float x){
    uint32_t r; asm("cvt.rna.tf32.f32 %0, %1;" : "=r"(r) : "f"(x)); return r;
}
__device__ __forceinline__ void mma_tf32(float c[4], const uint32_t a[4], const uint32_t b[2]){
    asm volatile(
        "mma.sync.aligned.m16n8k8.row.col.f32.tf32.tf32.f32 "
        "{%0,%1,%2,%3},{%4,%5,%6,%7},{%8,%9},{%0,%1,%2,%3};"
        : "+f"(c[0]), "+f"(c[1]), "+f"(c[2]), "+f"(c[3])
        : "r"(a[0]), "r"(a[1]), "r"(a[2]), "r"(a[3]), "r"(b[0]), "r"(b[1]));
}
// pixel index read/written by scan direction k at global step T
__device__ __forceinline__ int pmap(int k, int T){
    int t = (k & 2) ? (LL - 1 - T) : T;
    return (k & 1) ? ((t & 63) * 64 + (t >> 6)) : t;
}

// -------------------- LN row stats --------------------
template<int D>
__global__ void ln_stats(const float* __restrict__ x, float2* __restrict__ st){
    int row = blockIdx.x;
    float v = x[(size_t)row * D + threadIdx.x];
    float s1 = v, s2 = v * v;
    #pragma unroll
    for (int o = 16; o; o >>= 1){
        s1 += __shfl_xor_sync(0xffffffffu, s1, o);
        s2 += __shfl_xor_sync(0xffffffffu, s2, o);
    }
    __shared__ float r1[D/32], r2[D/32];
    int w = threadIdx.x >> 5;
    if ((threadIdx.x & 31) == 0){ r1[w] = s1; r2[w] = s2; }
    __syncthreads();
    if (threadIdx.x == 0){
        float a = 0.f, b = 0.f;
        #pragma unroll
        for (int i = 0; i < D/32; i++){ a += r1[i]; b += r2[i]; }
        float mu = a / D;
        float var = b / D - mu * mu;
        st[row] = make_float2(mu, rsqrtf(var + 1e-5f));
    }
}

// -------------------- TF32 tensor-core GEMM with fused epilogues --------------------
// C[M,N] = op(A)[M,K] * B[K,N].  BM = MT*64, BN = 128, BK = 32, 256 thr.
// Smem stride 136 (=8 mod 32) + XOR swizzle (idx ^ (k & 28)) -> conflict-free.
// NORMA: LN A on load. BT: B stored [N][K]. EPI: 0 plain(+Nguard) | 1 split/silu | 2 bias+gelu | 3 bias?+residual
template<int MT, bool NORMA, bool BT, int EPI>
__global__ void __launch_bounds__(256, 2) gemm_tc(
    const float* __restrict__ A, const float* __restrict__ Bm, float* __restrict__ Cmat,
    int M, int Nn, int Kk,
    const float2* __restrict__ stats, const float* __restrict__ nw, const float* __restrict__ nb,
    const float* __restrict__ bias, const float* __restrict__ res, float* __restrict__ out2)
{
    constexpr int BM = MT * 64;
    constexpr int SST = 136;            // smem row stride (uint32 units)
    __shared__ uint32_t As[32 * SST];
    __shared__ uint32_t Bs[32 * SST];

    const int tid = threadIdx.x;
    const int lane = tid & 31, wid = tid >> 5;
    const int wm = wid & 3, wn = wid >> 2;     // 4 x 2 warp grid
    const int t = lane & 3, g = lane >> 2;
    const int bm = blockIdx.y * BM;
    const int bn = blockIdx.x * 128;

    float acc[MT][8][4];
    #pragma unroll
    for (int i = 0; i < MT; i++)
        #pragma unroll
        for (int j = 0; j < 8; j++)
            #pragma unroll
            for (int e = 0; e < 4; e++) acc[i][j][e] = 0.f;

    for (int kt = 0; kt < Kk; kt += 32){
        // ---- A tile: BM x 32, float4 along K, transpose into As[k][m ^ (k&28)] ----
        #pragma unroll
        for (int q = 0; q < 2 * MT; q++){
            int idx = q * 256 + tid;
            int row = idx >> 3;
            int c4  = idx & 7;
            float4 v = *reinterpret_cast<const float4*>(
                &A[(size_t)(bm + row) * Kk + kt + c4 * 4]);
            float vv[4] = {v.x, v.y, v.z, v.w};
            if (NORMA){
                float2 stv = stats[bm + row];
                #pragma unroll
                for (int e = 0; e < 4; e++){
                    int kg = kt + c4 * 4 + e;
                    vv[e] = (vv[e] - stv.x) * stv.y * nw[kg] + nb[kg];
                }
            }
            #pragma unroll
            for (int e = 0; e < 4; e++){
                int kk = c4 * 4 + e;
                As[kk * SST + (row ^ (c4 * 4))] = f2tf32(vv[e]);
            }
        }
        // ---- B tile: 32 x 128 ----
        if (!BT){
            #pragma unroll
            for (int q = 0; q < 4; q++){
                int idx = q * 256 + tid;
                int row = idx >> 5;          // k
                int c4  = idx & 31;          // n/4
                float4 v = *reinterpret_cast<const float4*>(
                    &Bm[(size_t)(kt + row) * Nn + bn + c4 * 4]);
                uint4 u = make_uint4(f2tf32(v.x), f2tf32(v.y), f2tf32(v.z), f2tf32(v.w));
                *reinterpret_cast<uint4*>(&Bs[row * SST + ((c4 * 4) ^ (row & 28))]) = u;
            }
        } else {
            #pragma unroll
            for (int q = 0; q < 4; q++){
                int idx = q * 256 + tid;
                int nl = idx >> 3;           // n in tile
                int c4 = idx & 7;            // k/4
                float4 v = make_float4(0.f, 0.f, 0.f, 0.f);
                if (bn + nl < Nn)
                    v = *reinterpret_cast<const float4*>(
                        &Bm[(size_t)(bn + nl) * Kk + kt + c4 * 4]);
                float vv[4] = {v.x, v.y, v.z, v.w};
                #pragma unroll
                for (int e = 0; e < 4; e++){
                    int kk = c4 * 4 + e;
                    Bs[kk * SST + (nl ^ (c4 * 4))] = f2tf32(vv[e]);
                }
            }
        }
        __syncthreads();

        // ---- compute: 4 k8-steps ----
        #pragma unroll
        for (int ks = 0; ks < 4; ks++){
            int kb = ks * 8;
            int k0 = kb + t, k1 = kb + 4 + t;
            int x0 = kb & 28, x1 = (kb + 4) & 28;   // k&28 const per instr
            uint32_t afr[MT][4];
            #pragma unroll
            for (int mt = 0; mt < MT; mt++){
                int mr = wm * (MT * 16) + mt * 16 + g;
                afr[mt][0] = As[k0 * SST + (mr ^ x0)];
                afr[mt][1] = As[k0 * SST + ((mr + 8) ^ x0)];
                afr[mt][2] = As[k1 * SST + (mr ^ x1)];
                afr[mt][3] = As[k1 * SST + ((mr + 8) ^ x1)];
            }
            uint32_t bfr[8][2];
            #pragma unroll
            for (int nt = 0; nt < 8; nt++){
                int nc = wn * 64 + nt * 8 + g;
                bfr[nt][0] = Bs[k0 * SST + (nc ^ x0)];
                bfr[nt][1] = Bs[k1 * SST + (nc ^ x1)];
            }
            #pragma unroll
            for (int mt = 0; mt < MT; mt++)
                #pragma unroll
                for (int nt = 0; nt < 8; nt++)
                    mma_tf32(acc[mt][nt], afr[mt], bfr[nt]);
        }
        __syncthreads();
    }

    // ---- epilogue (pairs are float2-aligned: col even) ----
    #pragma unroll
    for (int mt = 0; mt < MT; mt++){
        #pragma unroll
        for (int nt = 0; nt < 8; nt++){
            int r0 = bm + wm * (MT * 16) + mt * 16 + g;
            int c0 = bn + wn * 64 + nt * 8 + 2 * t;
            #pragma unroll
            for (int h = 0; h < 2; h++){
                int r = r0 + h * 8;
                float v0 = acc[mt][nt][h * 2 + 0];
                float v1 = acc[mt][nt][h * 2 + 1];
                if (EPI == 1){
                    if (c0 < 256){
                        *reinterpret_cast<float2*>(&Cmat[(size_t)r * 256 + c0]) =
                            make_float2(v0, v1);
                    } else {
                        *reinterpret_cast<float2*>(&out2[(size_t)r * 256 + (c0 - 256)]) =
                            make_float2(silu_f(v0), silu_f(v1));
                    }
                } else if (EPI == 2){
                    v0 = gelu_f(v0 + bias[c0]);
                    v1 = gelu_f(v1 + bias[c0 + 1]);
                    *reinterpret_cast<float2*>(&Cmat[(size_t)r * Nn + c0]) =
                        make_float2(v0, v1);
                } else if (EPI == 3){
                    if (bias){ v0 += bias[c0]; v1 += bias[c0 + 1]; }
                    float2 rv = *reinterpret_cast<const float2*>(&res[(size_t)r * Nn + c0]);
                    *reinterpret_cast<float2*>(&Cmat[(size_t)r * Nn + c0]) =
                        make_float2(v0 + rv.x, v1 + rv.y);
                } else {
                    if (c0 < Nn)
                        *reinterpret_cast<float2*>(&Cmat[(size_t)r * Nn + c0]) =
                            make_float2(v0, v1);
                }
            }
        }
    }
}

// -------------------- depthwise 3x3 conv + bias + SiLU --------------------
__global__ void conv_dw(const float* __restrict__ wc, const float* __restrict__ bc){
    int pix = blockIdx.x;
    int d = threadIdx.x;
    int b = pix >> 12;
    int l = pix & (LL - 1);
    int h = l >> 6;
    int w = l & 63;
    float acc = bc[d];
    #pragma unroll
    for (int dy = -1; dy <= 1; dy++){
        int hh = h + dy;
        if (hh < 0 || hh >= HH) continue;
        #pragma unroll
        for (int dx = -1; dx <= 1; dx++){
            int w2 = w + dx;
            if (w2 < 0 || w2 >= WW) continue;
            acc = fmaf(wc[d * 9 + (dy + 1) * 3 + (dx + 1)],
                       g_x1[((size_t)(b * LL + hh * WW + w2)) * DI + d], acc);
        }
    }
    g_xc[(size_t)pix * DI + d] = silu_f(acc);
}

__global__ void zero_y(){
    size_t i = (size_t)blockIdx.x * 256 + threadIdx.x;
    g_y[i] = 0.f;
}

// -------------------- selective scan: pass 1 (chunk-local) --------------------
__global__ void __launch_bounds__(256) scan_pass1(
    const float* __restrict__ dtw, const float* __restrict__ dtb,
    const float* __restrict__ alog)
{
    int bk = blockIdx.x;
    int chunk = blockIdx.y;
    int b = bk >> 2, k = bk & 3;
    int d = threadIdx.x;
    __shared__ float tile[CS * 40];
    int T0 = chunk * CS;
    for (int i = d; i < CS * 40; i += 256){
        int t = i / 40, c = i - t * 40;
        int p = pmap(k, T0 + t);
        tile[i] = g_xd[(size_t)(b * LL + p) * 160 + k * 40 + c];
    }
    __syncthreads();

    float dw[RR];
    #pragma unroll
    for (int r = 0; r < RR; r++) dw[r] = dtw[(size_t)(k * DI + d) * RR + r];
    float db = dtb[k * DI + d];
    float Av[NS];
    #pragma unroll
    for (int n = 0; n < NS; n++) Av[n] = -__expf(alog[(size_t)(k * DI + d) * NS + n]);
    float A0 = Av[0];
    bool fast = true;
    #pragma unroll
    for (int n = 0; n < NS; n++){
        float e = Av[n] - (float)(n + 1) * A0;
        if (fabsf(e) > 1e-5f * fabsf(Av[n]) + 1e-12f) fast = false;
    }
    float S[NS];
    #pragma unroll
    for (int n = 0; n < NS; n++) S[n] = 0.f;
    float dsum = 0.f;

    for (int t = 0; t < CS; t++){
        int p = pmap(k, T0 + t);
        float xt = g_xc[(size_t)(b * LL + p) * DI + d];
        const float* tr = &tile[t * 40];
        float dp = db;
        #pragma unroll
        for (int r = 0; r < RR; r++) dp = fmaf(dw[r], tr[r], dp);
        float delta = softplus_f(dp);
        dsum += delta;
        float du = delta * xt;
        if (fast){
            float gg = __expf(delta * A0);
            float a = gg;
            #pragma unroll
            for (int n = 0; n < NS; n++){
                S[n] = fmaf(a, S[n], du * tr[8 + n]);
                a *= gg;
            }
        } else {
            #pragma unroll
            for (int n = 0; n < NS; n++){
                float a = __expf(delta * Av[n]);
                S[n] = fmaf(a, S[n], du * tr[8 + n]);
            }
        }
    }
    size_t base = ((size_t)(bk * NCH + chunk) * NS) * DI + d;
    #pragma unroll
    for (int n = 0; n < NS; n++){
        g_P[base + (size_t)n * DI] = __expf(dsum * Av[n]);
        g_S[base + (size_t)n * DI] = S[n];
    }
}

// -------------------- scan pass 2: carry across chunks --------------------
__global__ void scan_pass2(){
    int id = blockIdx.x * 256 + threadIdx.x;
    int d  = id & 255;
    int n  = (id >> 8) & 15;
    int bk = id >> 12;
    float Hc = 0.f;
    size_t stride = (size_t)NS * DI;
    size_t base = ((size_t)bk * NCH * NS + n) * DI + d;
    for (int c = 0; c < NCH; c++){
        size_t a = base + (size_t)c * stride;
        float Pv = g_P[a];
        float Sv = g_S[a];
        g_S[a] = Hc;
        Hc = fmaf(Pv, Hc, Sv);
    }
}

// -------------------- scan pass 3: replay + y + merge (atomic) --------------------
__global__ void __launch_bounds__(256) scan_pass3(
    const float* __restrict__ dtw, const float* __restrict__ dtb,
    const float* __restrict__ alog, const float* __restrict__ Dsv)
{
    int bk = blockIdx.x;
    int chunk = blockIdx.y;
    int b = bk >> 2, k = bk & 3;
    int d = threadIdx.x;
    __shared__ float tile[CS * 40];
    int T0 = chunk * CS;
    for (int i = d; i < CS * 40; i += 256){
        int t = i / 40, c = i - t * 40;
        int p = pmap(k, T0 + t);
        tile[i] = g_xd[(size_t)(b * LL + p) * 160 + k * 40 + c];
    }
    __syncthreads();

    float dw[RR];
    #pragma unroll
    for (int r = 0; r < RR; r++) dw[r] = dtw[(size_t)(k * DI + d) * RR + r];
    float db = dtb[k * DI + d];
    float Dk = Dsv[k * DI + d];
    float Av[NS];
    #pragma unroll
    for (int n = 0; n < NS; n++) Av[n] = -__expf(alog[(size_t)(k * DI + d) * NS + n]);
    float A0 = Av[0];
    bool fast = true;
    #pragma unroll
    for (int n = 0; n < NS; n++){
        float e = Av[n] - (float)(n + 1) * A0;
        if (fabsf(e) > 1e-5f * fabsf(Av[n]) + 1e-12f) fast = false;
    }
    float h[NS];
    size_t base = ((size_t)(bk * NCH + chunk) * NS) * DI + d;
    #pragma unroll
    for (int n = 0; n < NS; n++) h[n] = g_S[base + (size_t)n * DI];

    for (int t = 0; t < CS; t++){
        int p = pmap(k, T0 + t);
        size_t pidx = (size_t)(b * LL + p) * DI + d;
        float xt = g_xc[pidx];
        const float* tr = &tile[t * 40];
        float dp = db;
        #pragma unroll
        for (int r = 0; r < RR; r++) dp = fmaf(dw[r], tr[r], dp);
        float delta = softplus_f(dp);
        float du = delta * xt;
        float y = 0.f;
        if (fast){
            float gg = __expf(delta * A0);
            float a = gg;
            #pragma unroll
            for (int n = 0; n < NS; n++){
                h[n] = fmaf(a, h[n], du * tr[8 + n]);
                y = fmaf(h[n], tr[24 + n], y);
                a *= gg;
            }
        } else {
            #pragma unroll
            for (int n = 0; n < NS; n++){
                float a = __expf(delta * Av[n]);
                h[n] = fmaf(a, h[n], du * tr[8 + n]);
                y = fmaf(h[n], tr[24 + n], y);
            }
        }
        y = fmaf(Dk, xt, y);
        atomicAdd(&g_y[pidx], y);
    }
}

// -------------------- out-norm (LN over DI) * silu(z) --------------------
__global__ void onorm_mul(const float* __restrict__ onw, const float* __restrict__ onb){
    int row = blockIdx.x;
    int d = threadIdx.x;
    float v = g_y[(size_t)row * DI + d];
    float s1 = v, s2 = v * v;
    #pragma unroll
    for (int o = 16; o; o >>= 1){
        s1 += __shfl_xor_sync(0xffffffffu, s1, o);
        s2 += __shfl_xor_sync(0xffffffffu, s2, o);
    }
    __shared__ float r1[8], r2[8];
    int w = d >> 5;
    if ((d & 31) == 0){ r1[w] = s1; r2[w] = s2; }
    __syncthreads();
    float a = 0.f, bsum = 0.f;
    #pragma unroll
    for (int i = 0; i < 8; i++){ a += r1[i]; bsum += r2[i]; }
    float mu = a / DI;
    float var = bsum / DI - mu * mu;
    float rs = rsqrtf(var + 1e-5f);
    float o = (v - mu) * rs * onw[d] + onb[d];
    g_yn[(size_t)row * DI + d] = o * g_sz[(size_t)row * DI + d];
}

// -------------------- host launch --------------------
extern "C" void kernel_launch(void* const* d_in, const int* in_sizes, int n_in,
                              void* d_out, int out_size)
{
    (void)in_sizes; (void)n_in; (void)out_size;
    const float* input     = (const float*)d_in[0];
    const float* ln1_w     = (const float*)d_in[1];
    const float* ln1_b     = (const float*)d_in[2];
    const float* in_proj_w = (const float*)d_in[3];
    const float* conv_w    = (const float*)d_in[4];
    const float* conv_b    = (const float*)d_in[5];
    const float* x_proj_w  = (const float*)d_in[6];
    const float* dt_w      = (const float*)d_in[7];
    const float* dt_b      = (const float*)d_in[8];
    const float* A_log     = (const float*)d_in[9];
    const float* Ds        = (const float*)d_in[10];
    const float* onorm_w   = (const float*)d_in[11];
    const float* onorm_b   = (const float*)d_in[12];
    const float* out_proj_w= (const float*)d_in[13];
    const float* ln2_w     = (const float*)d_in[14];
    const float* ln2_b     = (const float*)d_in[15];
    const float* fc1_w     = (const float*)d_in[16];
    const float* fc1_b     = (const float*)d_in[17];
    const float* fc2_w     = (const float*)d_in[18];
    const float* fc2_b     = (const float*)d_in[19];

    float *px1, *psz, *pxc, *pxd, *pyn, *pxmid, *ph;
    float2 *pst1, *pst2;
    cudaGetSymbolAddress((void**)&px1,  g_x1);
    cudaGetSymbolAddress((void**)&psz,  g_sz);
    cudaGetSymbolAddress((void**)&pxc,  g_xc);
    cudaGetSymbolAddress((void**)&pxd,  g_xd);
    cudaGetSymbolAddress((void**)&pyn,  g_yn);
    cudaGetSymbolAddress((void**)&pxmid,g_xmid);
    cudaGetSymbolAddress((void**)&ph,   g_hbuf);
    cudaGetSymbolAddress((void**)&pst1, g_st1);
    cudaGetSymbolAddress((void**)&pst2, g_st2);

    // 1. LN1 stats + (LN1 -> in_proj) GEMM, split x_/silu(z)
    ln_stats<128><<<BL, 128>>>(input, pst1);
    gemm_tc<2, true, false, 1><<<dim3(4, 128), 256>>>(
        input, in_proj_w, px1, BL, 512, 128, pst1, ln1_w, ln1_b,
        nullptr, nullptr, psz);

    // 2. depthwise conv + bias + SiLU
    conv_dw<<<BL, 256>>>(conv_w, conv_b);

    // 3. x_proj (all 4 directions stacked): [BL,256]@[256,160]
    gemm_tc<2, false, true, 0><<<dim3(2, 128), 256>>>(
        pxc, x_proj_w, pxd, BL, 160, 256, nullptr, nullptr, nullptr,
        nullptr, nullptr, nullptr);

    // 4. selective scan (chunked) + merge
    zero_y<<<(BL * DI) / 256, 256>>>();
    scan_pass1<<<dim3(16, NCH), 256>>>(dt_w, dt_b, A_log);
    scan_pass2<<<256, 256>>>();
    scan_pass3<<<dim3(16, NCH), 256>>>(dt_w, dt_b, A_log, Ds);

    // 5. out-norm * silu(z), then out_proj + residual(input)
    onorm_mul<<<BL, 256>>>(onorm_w, onorm_b);
    gemm_tc<1, false, false, 3><<<dim3(1, 256), 256>>>(
        pyn, out_proj_w, pxmid, BL, 128, 256, nullptr, nullptr, nullptr,
        nullptr, input, nullptr);

    // 6. MLP: LN2 -> fc1+GELU -> fc2 + residual
    ln_stats<128><<<BL, 128>>>(pxmid, pst2);
    gemm_tc<2, true, false, 2><<<dim3(4, 128), 256>>>(
        pxmid, fc1_w, ph, BL, 512, 128, pst2, ln2_w, ln2_b,
        fc1_b, nullptr, nullptr);
    gemm_tc<1, false, false, 3><<<dim3(1, 256), 256>>>(
        ph, fc2_w, (float*)d_out, BL, 128, 512, nullptr, nullptr, nullptr,
        fc2_b, pxmid, nullptr);
}

// round 3
// speedup vs baseline: 1.5112x; 1.1017x over previous
#include <cuda_runtime.h>
#include <math.h>
#include <stdint.h>

// Problem constants
#define BQ 4
#define HH 64
#define WW 64
#define CC 128
#define DI 256
#define NS 16
#define RR 8
#define LL 4096       // H*W
#define BL (BQ*LL)    // 16384 pixel-rows
#define CS 128        // scan chunk size
#define NCH (LL/CS)   // 32 chunks

// -------------------- device scratch (static, no allocs) --------------------
__device__ __align__(16) float g_x1[BL*DI];        // x_ (conv input)
__device__ __align__(16) float g_sz[BL*DI];        // silu(z)
__device__ __align__(16) float g_xc[BL*DI];        // conv+silu output
__device__ __align__(16) float g_xd[BL*160];       // x_proj output per pixel
__device__ __align__(16) float g_y [BL*DI];        // scan merged output (atomic accum)
__device__ __align__(16) float g_yn[BL*DI];        // onorm(y) * silu(z)
__device__ __align__(16) float g_xmid[BL*CC];      // after out_proj + residual
__device__ __align__(16) float g_hbuf[BL*4*CC];    // MLP hidden
__device__ __align__(16) float g_xn1[BL*CC];       // LN1(input)
__device__ __align__(16) float g_xn2[BL*CC];       // LN2(xmid)
__device__ __align__(16) float g_xpw[256*256];     // x_proj_w transposed+padded [K=256][N=256]
__device__ __align__(16) float g_P[16*NCH*NS*DI];  // chunk decay products
__device__ __align__(16) float g_S[16*NCH*NS*DI];  // chunk states

// -------------------- small math helpers --------------------
__device__ __forceinline__ float silu_f(float x){ return x / (1.f + __expf(-x)); }
__device__ __forceinline__ float softplus_f(float x){
    return fmaxf(x, 0.f) + __logf(1.f + __expf(-fabsf(x)));
}
__device__ __forceinline__ float gelu_f(float x){
    return 0.5f * x * (1.f + erff(x * 0.70710678118654752f));
}
__device__ __forceinline__ void mma_tf32(float c[4], const uint32_t a[4], const uint32_t b[2]){
    asm volatile(
        "mma.sync.aligned.m16n8k8.row.col.f32.tf32.tf32.f32 "
        "{%0,%1,%2,%3},{%4,%5,%6,%7},{%8,%9},{%0,%1,%2,%3};"
        : "+f"(c[0]), "+f"(c[1]), "+f"(c[2]), "+f"(c[3])
        : "r"(a[0]), "r"(a[1]), "r"(a[2]), "r"(a[3]), "r"(b[0]), "r"(b[1]));
}
__device__ __forceinline__ void cp16(uint32_t dst, const void* src){
    asm volatile("cp.async.cg.shared.global [%0], [%1], 16;" :: "r"(dst), "l"(src));
}
// pixel index read/written by scan direction k at global step T
__device__ __forceinline__ int pmap(int k, int T){
    int t = (k & 2) ? (LL - 1 - T) : T;
    return (k & 1) ? ((t & 63) * 64 + (t >> 6)) : t;
}

// -------------------- LN (stats + write normalized rows) --------------------
__global__ void ln_norm(const float* __restrict__ x, float* __restrict__ xo,
                        const float* __restrict__ w, const float* __restrict__ b){
    int row = blockIdx.x;
    float v = x[(size_t)row * CC + threadIdx.x];
    float s1 = v, s2 = v * v;
    #pragma unroll
    for (int o = 16; o; o >>= 1){
        s1 += __shfl_xor_sync(0xffffffffu, s1, o);
        s2 += __shfl_xor_sync(0xffffffffu, s2, o);
    }
    __shared__ float r1[4], r2[4];
    int wi = threadIdx.x >> 5;
    if ((threadIdx.x & 31) == 0){ r1[wi] = s1; r2[wi] = s2; }
    __syncthreads();
    float a = 0.f, bb = 0.f;
    #pragma unroll
    for (int i = 0; i < 4; i++){ a += r1[i]; bb += r2[i]; }
    float mu = a / CC;
    float var = bb / CC - mu * mu;
    float rs = rsqrtf(var + 1e-5f);
    xo[(size_t)row * CC + threadIdx.x] =
        (v - mu) * rs * w[threadIdx.x] + b[threadIdx.x];
}

// -------------------- transpose + pad x_proj_w: [160][256] -> [256][256] --------------------
__global__ void xpw_transpose(const float* __restrict__ w){
    int d = blockIdx.x;        // 0..255 (K dim)
    int n = threadIdx.x;       // 0..255
    g_xpw[d * 256 + n] = (n < 160) ? w[(size_t)n * 256 + d] : 0.f;
}

// -------------------- TF32 tensor-core GEMM, cp.async 2-stage pipeline --------------------
// C[M,N] = A[M,K]*B[K,N].  BM=128, BN=128, BK=32, 256 thr, 4x2 warps.
// A smem [m][k] stride 36; B smem [k][n] stride 136. Raw fp32 bits into tf32 MMA.
// EPI: 0 plain(+Nguard) | 1 split x_/silu(z) | 2 bias+gelu | 3 bias?+residual
#define AST 36
#define BST 136
#define A_STG (128*AST)
#define B_STG (32*BST)
#define GEMM_SMEM ((2*A_STG + 2*B_STG) * 4)

template<int EPI>
__global__ void __launch_bounds__(256, 2) gemm_tc(
    const float* __restrict__ A, const float* __restrict__ Bm, float* __restrict__ Cmat,
    int M, int Nn, int Kk, int ldB,
    const float* __restrict__ bias, const float* __restrict__ res, float* __restrict__ out2)
{
    extern __shared__ float smem[];
    uint32_t sbase;
    { void* p = smem; sbase = (uint32_t)__cvta_generic_to_shared(p); }
    uint32_t* Ss = reinterpret_cast<uint32_t*>(smem);

    const int tid = threadIdx.x;
    const int lane = tid & 31, wid = tid >> 5;
    const int wm = wid & 3, wn = wid >> 2;     // 4 x 2 warp grid
    const int t = lane & 3, g = lane >> 2;
    const int bm = blockIdx.y * 128;
    const int bn = blockIdx.x * 128;

    const int arow = tid >> 3, ac4 = tid & 7;      // A: 4 chunks of (32 rows x full k)
    const int brow = tid >> 5, bc4 = tid & 31;     // B: 4 chunks of (8 rows x full n)

    float acc[2][8][4];
    #pragma unroll
    for (int i = 0; i < 2; i++)
        #pragma unroll
        for (int j = 0; j < 8; j++)
            #pragma unroll
            for (int e = 0; e < 4; e++) acc[i][j][e] = 0.f;

    const int nk = Kk >> 5;

    auto load_stage = [&](int stage, int kt){
        uint32_t abase = sbase + (stage * A_STG) * 4;
        #pragma unroll
        for (int q = 0; q < 4; q++){
            int row = q * 32 + arow;
            cp16(abase + (row * AST + ac4 * 4) * 4,
                 &A[(size_t)(bm + row) * Kk + kt + ac4 * 4]);
        }
        uint32_t bbase = sbase + (2 * A_STG + stage * B_STG) * 4;
        #pragma unroll
        for (int q = 0; q < 4; q++){
            int row = q * 8 + brow;
            cp16(bbase + (row * BST + bc4 * 4) * 4,
                 &Bm[(size_t)(kt + row) * ldB + bn + bc4 * 4]);
        }
    };

    load_stage(0, 0);
    asm volatile("cp.async.commit_group;");

    for (int i = 0; i < nk; i++){
        if (i + 1 < nk) load_stage((i + 1) & 1, (i + 1) << 5);
        asm volatile("cp.async.commit_group;");
        asm volatile("cp.async.wait_group 1;");
        __syncthreads();

        const uint32_t* Ab = Ss + (i & 1) * A_STG;
        const uint32_t* Bb = Ss + 2 * A_STG + (i & 1) * B_STG;
        #pragma unroll
        for (int ks = 0; ks < 4; ks++){
            int k0 = ks * 8 + t, k1 = k0 + 4;
            uint32_t afr[2][4];
            #pragma unroll
            for (int mt = 0; mt < 2; mt++){
                int mr = wm * 32 + mt * 16 + g;
                afr[mt][0] = Ab[mr * AST + k0];
                afr[mt][1] = Ab[(mr + 8) * AST + k0];
                afr[mt][2] = Ab[mr * AST + k1];
                afr[mt][3] = Ab[(mr + 8) * AST + k1];
            }
            uint32_t bfr[8][2];
            #pragma unroll
            for (int nt = 0; nt < 8; nt++){
                int nc = wn * 64 + nt * 8 + g;
                bfr[nt][0] = Bb[k0 * BST + nc];
                bfr[nt][1] = Bb[k1 * BST + nc];
            }
            #pragma unroll
            for (int mt = 0; mt < 2; mt++)
                #pragma unroll
                for (int nt = 0; nt < 8; nt++)
                    mma_tf32(acc[mt][nt], afr[mt], bfr[nt]);
        }
        __syncthreads();
    }

    // ---- epilogue (float2 stores; c0 always even) ----
    #pragma unroll
    for (int mt = 0; mt < 2; mt++){
        #pragma unroll
        for (int nt = 0; nt < 8; nt++){
            int r0 = bm + wm * 32 + mt * 16 + g;
            int c0 = bn + wn * 64 + nt * 8 + 2 * t;
            #pragma unroll
            for (int h = 0; h < 2; h++){
                int r = r0 + h * 8;
                float v0 = acc[mt][nt][h * 2 + 0];
                float v1 = acc[mt][nt][h * 2 + 1];
                if (EPI == 1){
                    if (c0 < 256)
                        *reinterpret_cast<float2*>(&Cmat[(size_t)r * 256 + c0]) =
                            make_float2(v0, v1);
                    else
                        *reinterpret_cast<float2*>(&out2[(size_t)r * 256 + (c0 - 256)]) =
                            make_float2(silu_f(v0), silu_f(v1));
                } else if (EPI == 2){
                    v0 = gelu_f(v0 + bias[c0]);
                    v1 = gelu_f(v1 + bias[c0 + 1]);
                    *reinterpret_cast<float2*>(&Cmat[(size_t)r * Nn + c0]) =
                        make_float2(v0, v1);
                } else if (EPI == 3){
                    if (bias){ v0 += bias[c0]; v1 += bias[c0 + 1]; }
                    float2 rv = *reinterpret_cast<const float2*>(&res[(size_t)r * Nn + c0]);
                    *reinterpret_cast<float2*>(&Cmat[(size_t)r * Nn + c0]) =
                        make_float2(v0 + rv.x, v1 + rv.y);
                } else {
                    if (c0 < Nn)
                        *reinterpret_cast<float2*>(&Cmat[(size_t)r * Nn + c0]) =
                            make_float2(v0, v1);
                }
            }
        }
    }
}

// -------------------- depthwise 3x3 conv + bias + SiLU --------------------
__global__ void conv_dw(const float* __restrict__ wc, const float* __restrict__ bc){
    int pix = blockIdx.x;
    int d = threadIdx.x;
    int b = pix >> 12;
    int l = pix & (LL - 1);
    int h = l >> 6;
    int w = l & 63;
    float acc = bc[d];
    #pragma unroll
    for (int dy = -1; dy <= 1; dy++){
        int hh = h + dy;
        if (hh < 0 || hh >= HH) continue;
        #pragma unroll
        for (int dx = -1; dx <= 1; dx++){
            int w2 = w + dx;
            if (w2 < 0 || w2 >= WW) continue;
            acc = fmaf(wc[d * 9 + (dy + 1) * 3 + (dx + 1)],
                       g_x1[((size_t)(b * LL + hh * WW + w2)) * DI + d], acc);
        }
    }
    g_xc[(size_t)pix * DI + d] = silu_f(acc);
}

__global__ void zero_y(){
    size_t i = (size_t)blockIdx.x * 256 + threadIdx.x;
    g_y[i] = 0.f;
}

// -------------------- selective scan: pass 1 (chunk-local) --------------------
__global__ void __launch_bounds__(256) scan_pass1(
    const float* __restrict__ dtw, const float* __restrict__ dtb,
    const float* __restrict__ alog)
{
    int bk = blockIdx.x;
    int chunk = blockIdx.y;
    int b = bk >> 2, k = bk & 3;
    int d = threadIdx.x;
    __shared__ float tile[CS * 40];
    int T0 = chunk * CS;
    for (int i = d; i < CS * 40; i += 256){
        int t = i / 40, c = i - t * 40;
        int p = pmap(k, T0 + t);
        tile[i] = g_xd[(size_t)(b * LL + p) * 160 + k * 40 + c];
    }
    __syncthreads();

    float dw[RR];
    #pragma unroll
    for (int r = 0; r < RR; r++) dw[r] = dtw[(size_t)(k * DI + d) * RR + r];
    float db = dtb[k * DI + d];
    float Av[NS];
    #pragma unroll
    for (int n = 0; n < NS; n++) Av[n] = -__expf(alog[(size_t)(k * DI + d) * NS + n]);
    float A0 = Av[0];
    bool fast = true;
    #pragma unroll
    for (int n = 0; n < NS; n++){
        float e = Av[n] - (float)(n + 1) * A0;
        if (fabsf(e) > 1e-5f * fabsf(Av[n]) + 1e-12f) fast = false;
    }
    float S[NS];
    #pragma unroll
    for (int n = 0; n < NS; n++) S[n] = 0.f;
    float dsum = 0.f;

    for (int t = 0; t < CS; t++){
        int p = pmap(k, T0 + t);
        float xt = g_xc[(size_t)(b * LL + p) * DI + d];
        const float* tr = &tile[t * 40];
        float dp = db;
        #pragma unroll
        for (int r = 0; r < RR; r++) dp = fmaf(dw[r], tr[r], dp);
        float delta = softplus_f(dp);
        dsum += delta;
        float du = delta * xt;
        if (fast){
            float gg = __expf(delta * A0);
            float a = gg;
            #pragma unroll
            for (int n = 0; n < NS; n++){
                S[n] = fmaf(a, S[n], du * tr[8 + n]);
                a *= gg;
            }
        } else {
            #pragma unroll
            for (int n = 0; n < NS; n++){
                float a = __expf(delta * Av[n]);
                S[n] = fmaf(a, S[n], du * tr[8 + n]);
            }
        }
    }
    size_t base = ((size_t)(bk * NCH + chunk) * NS) * DI + d;
    #pragma unroll
    for (int n = 0; n < NS; n++){
        g_P[base + (size_t)n * DI] = __expf(dsum * Av[n]);
        g_S[base + (size_t)n * DI] = S[n];
    }
}

// -------------------- scan pass 2: carry across chunks --------------------
__global__ void scan_pass2(){
    int id = blockIdx.x * 256 + threadIdx.x;
    int d  = id & 255;
    int n  = (id >> 8) & 15;
    int bk = id >> 12;
    float Hc = 0.f;
    size_t stride = (size_t)NS * DI;
    size_t base = ((size_t)bk * NCH * NS + n) * DI + d;
    for (int c = 0; c < NCH; c++){
        size_t a = base + (size_t)c * stride;
        float Pv = g_P[a];
        float Sv = g_S[a];
        g_S[a] = Hc;
        Hc = fmaf(Pv, Hc, Sv);
    }
}

// -------------------- scan pass 3: replay + y + merge (atomic) --------------------
__global__ void __launch_bounds__(256) scan_pass3(
    const float* __restrict__ dtw, const float* __restrict__ dtb,
    const float* __restrict__ alog, const float* __restrict__ Dsv)
{
    int bk = blockIdx.x;
    int chunk = blockIdx.y;
    int b = bk >> 2, k = bk & 3;
    int d = threadIdx.x;
    __shared__ float tile[CS * 40];
    int T0 = chunk * CS;
    for (int i = d; i < CS * 40; i += 256){
        int t = i / 40, c = i - t * 40;
        int p = pmap(k, T0 + t);
        tile[i] = g_xd[(size_t)(b * LL + p) * 160 + k * 40 + c];
    }
    __syncthreads();

    float dw[RR];
    #pragma unroll
    for (int r = 0; r < RR; r++) dw[r] = dtw[(size_t)(k * DI + d) * RR + r];
    float db = dtb[k * DI + d];
    float Dk = Dsv[k * DI + d];
    float Av[NS];
    #pragma unroll
    for (int n = 0; n < NS; n++) Av[n] = -__expf(alog[(size_t)(k * DI + d) * NS + n]);
    float A0 = Av[0];
    bool fast = true;
    #pragma unroll
    for (int n = 0; n < NS; n++){
        float e = Av[n] - (float)(n + 1) * A0;
        if (fabsf(e) > 1e-5f * fabsf(Av[n]) + 1e-12f) fast = false;
    }
    float h[NS];
    size_t base = ((size_t)(bk * NCH + chunk) * NS) * DI + d;
    #pragma unroll
    for (int n = 0; n < NS; n++) h[n] = g_S[base + (size_t)n * DI];

    for (int t = 0; t < CS; t++){
        int p = pmap(k, T0 + t);
        size_t pidx = (size_t)(b * LL + p) * DI + d;
        float xt = g_xc[pidx];
        const float* tr = &tile[t * 40];
        float dp = db;
        #pragma unroll
        for (int r = 0; r < RR; r++) dp = fmaf(dw[r], tr[r], dp);
        float delta = softplus_f(dp);
        float du = delta * xt;
        float y = 0.f;
        if (fast){
            float gg = __expf(delta * A0);
            float a = gg;
            #pragma unroll
            for (int n = 0; n < NS; n++){
                h[n] = fmaf(a, h[n], du * tr[8 + n]);
                y = fmaf(h[n], tr[24 + n], y);
                a *= gg;
            }
        } else {
            #pragma unroll
            for (int n = 0; n < NS; n++){
                float a = __expf(delta * Av[n]);
                h[n] = fmaf(a, h[n], du * tr[8 + n]);
                y = fmaf(h[n], tr[24 + n], y);
            }
        }
        y = fmaf(Dk, xt, y);
        atomicAdd(&g_y[pidx], y);
    }
}

// -------------------- out-norm (LN over DI) * silu(z) --------------------
__global__ void onorm_mul(const float* __restrict__ onw, const float* __restrict__ onb){
    int row = blockIdx.x;
    int d = threadIdx.x;
    float v = g_y[(size_t)row * DI + d];
    float s1 = v, s2 = v * v;
    #pragma unroll
    for (int o = 16; o; o >>= 1){
        s1 += __shfl_xor_sync(0xffffffffu, s1, o);
        s2 += __shfl_xor_sync(0xffffffffu, s2, o);
    }
    __shared__ float r1[8], r2[8];
    int w = d >> 5;
    if ((d & 31) == 0){ r1[w] = s1; r2[w] = s2; }
    __syncthreads();
    float a = 0.f, bsum = 0.f;
    #pragma unroll
    for (int i = 0; i < 8; i++){ a += r1[i]; bsum += r2[i]; }
    float mu = a / DI;
    float var = bsum / DI - mu * mu;
    float rs = rsqrtf(var + 1e-5f);
    float o = (v - mu) * rs * onw[d] + onb[d];
    g_yn[(size_t)row * DI + d] = o * g_sz[(size_t)row * DI + d];
}

// -------------------- host launch --------------------
extern "C" void kernel_launch(void* const* d_in, const int* in_sizes, int n_in,
                              void* d_out, int out_size)
{
    (void)in_sizes; (void)n_in; (void)out_size;
    const float* input     = (const float*)d_in[0];
    const float* ln1_w     = (const float*)d_in[1];
    const float* ln1_b     = (const float*)d_in[2];
    const float* in_proj_w = (const float*)d_in[3];
    const float* conv_w    = (const float*)d_in[4];
    const float* conv_b    = (const float*)d_in[5];
    const float* x_proj_w  = (const float*)d_in[6];
    const float* dt_w      = (const float*)d_in[7];
    const float* dt_b      = (const float*)d_in[8];
    const float* A_log     = (const float*)d_in[9];
    const float* Ds        = (const float*)d_in[10];
    const float* onorm_w   = (const float*)d_in[11];
    const float* onorm_b   = (const float*)d_in[12];
    const float* out_proj_w= (const float*)d_in[13];
    const float* ln2_w     = (const float*)d_in[14];
    const float* ln2_b     = (const float*)d_in[15];
    const float* fc1_w     = (const float*)d_in[16];
    const float* fc1_b     = (const float*)d_in[17];
    const float* fc2_w     = (const float*)d_in[18];
    const float* fc2_b     = (const float*)d_in[19];

    float *px1, *psz, *pxc, *pxd, *pyn, *pxmid, *ph, *pxn1, *pxn2, *pxpw;
    cudaGetSymbolAddress((void**)&px1,  g_x1);
    cudaGetSymbolAddress((void**)&psz,  g_sz);
    cudaGetSymbolAddress((void**)&pxc,  g_xc);
    cudaGetSymbolAddress((void**)&pxd,  g_xd);
    cudaGetSymbolAddress((void**)&pyn,  g_yn);
    cudaGetSymbolAddress((void**)&pxmid,g_xmid);
    cudaGetSymbolAddress((void**)&ph,   g_hbuf);
    cudaGetSymbolAddress((void**)&pxn1, g_xn1);
    cudaGetSymbolAddress((void**)&pxn2, g_xn2);
    cudaGetSymbolAddress((void**)&pxpw, g_xpw);

    static bool attr_done = false;
    if (!attr_done){
        cudaFuncSetAttribute(gemm_tc<0>, cudaFuncAttributeMaxDynamicSharedMemorySize, GEMM_SMEM);
        cudaFuncSetAttribute(gemm_tc<1>, cudaFuncAttributeMaxDynamicSharedMemorySize, GEMM_SMEM);
        cudaFuncSetAttribute(gemm_tc<2>, cudaFuncAttributeMaxDynamicSharedMemorySize, GEMM_SMEM);
        cudaFuncSetAttribute(gemm_tc<3>, cudaFuncAttributeMaxDynamicSharedMemorySize, GEMM_SMEM);
        attr_done = true;
    }

    // 0. transpose x_proj weights (tiny)
    xpw_transpose<<<256, 256>>>(x_proj_w);

    // 1. LN1 -> in_proj GEMM, split x_/silu(z)
    ln_norm<<<BL, 128>>>(input, pxn1, ln1_w, ln1_b);
    gemm_tc<1><<<dim3(4, 128), 256, GEMM_SMEM>>>(
        pxn1, in_proj_w, px1, BL, 512, 128, 512, nullptr, nullptr, psz);

    // 2. depthwise conv + bias + SiLU
    conv_dw<<<BL, 256>>>(conv_w, conv_b);

    // 3. x_proj: [BL,256]@[256,160] (B padded to 256 cols)
    gemm_tc<0><<<dim3(2, 128), 256, GEMM_SMEM>>>(
        pxc, pxpw, pxd, BL, 160, 256, 256, nullptr, nullptr, nullptr);

    // 4. selective scan (chunked) + merge
    zero_y<<<(BL * DI) / 256, 256>>>();
    scan_pass1<<<dim3(16, NCH), 256>>>(dt_w, dt_b, A_log);
    scan_pass2<<<256, 256>>>();
    scan_pass3<<<dim3(16, NCH), 256>>>(dt_w, dt_b, A_log, Ds);

    // 5. out-norm * silu(z), then out_proj + residual(input)
    onorm_mul<<<BL, 256>>>(onorm_w, onorm_b);
    gemm_tc<3><<<dim3(1, 128), 256, GEMM_SMEM>>>(
        pyn, out_proj_w, pxmid, BL, 128, 256, 128, nullptr, input, nullptr);

    // 6. MLP: LN2 -> fc1+GELU -> fc2 + residual
    ln_norm<<<BL, 128>>>(pxmid, pxn2, ln2_w, ln2_b);
    gemm_tc<2><<<dim3(4, 128), 256, GEMM_SMEM>>>(
        pxn2, fc1_w, ph, BL, 512, 128, 512, fc1_b, nullptr, nullptr);
    gemm_tc<3><<<dim3(1, 128), 256, GEMM_SMEM>>>(
        ph, fc2_w, (float*)d_out, BL, 128, 512, 128, fc2_b, pxmid, nullptr);
}

// round 4
// speedup vs baseline: 1.5512x; 1.0265x over previous
#include <cuda_runtime.h>
#include <math.h>
#include <stdint.h>

// Problem constants
#define BQ 4
#define HH 64
#define WW 64
#define CC 128
#define DI 256
#define NS 16
#define RR 8
#define LL 4096       // H*W
#define BL (BQ*LL)    // 16384 pixel-rows
#define CS 128        // scan chunk size
#define NCH (LL/CS)   // 32 chunks

// -------------------- device scratch (static, no allocs) --------------------
__device__ __align__(16) float g_x1[BL*DI];        // x_ (conv input)
__device__ __align__(16) float g_sz[BL*DI];        // silu(z)
__device__ __align__(16) float g_xc[BL*DI];        // conv+silu output
__device__ __align__(16) float g_xd[BL*160];       // x_proj output per pixel
__device__ __align__(16) float g_y [BL*DI];        // scan merged output (atomic accum)
__device__ __align__(16) float g_yn[BL*DI];        // onorm(y) * silu(z)
__device__ __align__(16) float g_xmid[BL*CC];      // after out_proj + residual
__device__ __align__(16) float g_hbuf[BL*4*CC];    // MLP hidden
__device__ __align__(16) float g_xn1[BL*CC];       // LN1(input)
__device__ __align__(16) float g_xn2[BL*CC];       // LN2(xmid)
__device__ __align__(16) float g_xpw[256*256];     // x_proj_w transposed+padded
__device__ __align__(16) float g_P[16*NCH*NS*DI];  // chunk decay products
__device__ __align__(16) float g_S[16*NCH*NS*DI];  // chunk states

// -------------------- small math helpers --------------------
__device__ __forceinline__ float silu_f(float x){ return x / (1.f + __expf(-x)); }
__device__ __forceinline__ float softplus_f(float x){
    return fmaxf(x, 0.f) + __logf(1.f + __expf(-fabsf(x)));
}
__device__ __forceinline__ float gelu_f(float x){
    return 0.5f * x * (1.f + erff(x * 0.70710678118654752f));
}
__device__ __forceinline__ void mma_tf32(float c[4], const uint32_t a[4], const uint32_t b[2]){
    asm volatile(
        "mma.sync.aligned.m16n8k8.row.col.f32.tf32.tf32.f32 "
        "{%0,%1,%2,%3},{%4,%5,%6,%7},{%8,%9},{%0,%1,%2,%3};"
        : "+f"(c[0]), "+f"(c[1]), "+f"(c[2]), "+f"(c[3])
        : "r"(a[0]), "r"(a[1]), "r"(a[2]), "r"(a[3]), "r"(b[0]), "r"(b[1]));
}
__device__ __forceinline__ void cp16(uint32_t dst, const void* src){
    asm volatile("cp.async.cg.shared.global [%0], [%1], 16;" :: "r"(dst), "l"(src));
}
// packed f32x2
__device__ __forceinline__ uint64_t pk2(float lo, float hi){
    uint64_t r; asm("mov.b64 %0, {%1,%2};" : "=l"(r) : "f"(lo), "f"(hi)); return r;
}
__device__ __forceinline__ void upk2(float& lo, float& hi, uint64_t v){
    asm("mov.b64 {%0,%1}, %2;" : "=f"(lo), "=f"(hi) : "l"(v));
}
__device__ __forceinline__ uint64_t mul2(uint64_t a, uint64_t b){
    uint64_t r; asm("mul.rn.f32x2 %0,%1,%2;" : "=l"(r) : "l"(a), "l"(b)); return r;
}
__device__ __forceinline__ uint64_t fma2(uint64_t a, uint64_t b, uint64_t c){
    uint64_t r; asm("fma.rn.f32x2 %0,%1,%2,%3;" : "=l"(r) : "l"(a), "l"(b), "l"(c)); return r;
}
// pixel index read/written by scan direction k at global step T
__device__ __forceinline__ int pmap(int k, int T){
    int t = (k & 2) ? (LL - 1 - T) : T;
    return (k & 1) ? ((t & 63) * 64 + (t >> 6)) : t;
}

// -------------------- LN (stats + write normalized rows) --------------------
__global__ void ln_norm(const float* __restrict__ x, float* __restrict__ xo,
                        const float* __restrict__ w, const float* __restrict__ b){
    int row = blockIdx.x;
    float v = x[(size_t)row * CC + threadIdx.x];
    float s1 = v, s2 = v * v;
    #pragma unroll
    for (int o = 16; o; o >>= 1){
        s1 += __shfl_xor_sync(0xffffffffu, s1, o);
        s2 += __shfl_xor_sync(0xffffffffu, s2, o);
    }
    __shared__ float r1[4], r2[4];
    int wi = threadIdx.x >> 5;
    if ((threadIdx.x & 31) == 0){ r1[wi] = s1; r2[wi] = s2; }
    __syncthreads();
    float a = 0.f, bb = 0.f;
    #pragma unroll
    for (int i = 0; i < 4; i++){ a += r1[i]; bb += r2[i]; }
    float mu = a / CC;
    float var = bb / CC - mu * mu;
    float rs = rsqrtf(var + 1e-5f);
    xo[(size_t)row * CC + threadIdx.x] =
        (v - mu) * rs * w[threadIdx.x] + b[threadIdx.x];
}

// -------------------- transpose + pad x_proj_w: [160][256] -> [256][256] --------------------
__global__ void xpw_transpose(const float* __restrict__ w){
    int d = blockIdx.x;
    int n = threadIdx.x;
    g_xpw[d * 256 + n] = (n < 160) ? w[(size_t)n * 256 + d] : 0.f;
}

// -------------------- TF32 tensor-core GEMM, cp.async 2-stage pipeline --------------------
#define AST 36
#define BST 136
#define A_STG (128*AST)
#define B_STG (32*BST)
#define GEMM_SMEM ((2*A_STG + 2*B_STG) * 4)

template<int EPI>
__global__ void __launch_bounds__(256, 2) gemm_tc(
    const float* __restrict__ A, const float* __restrict__ Bm, float* __restrict__ Cmat,
    int M, int Nn, int Kk, int ldB,
    const float* __restrict__ bias, const float* __restrict__ res, float* __restrict__ out2)
{
    extern __shared__ float smem[];
    uint32_t sbase;
    { void* p = smem; sbase = (uint32_t)__cvta_generic_to_shared(p); }
    uint32_t* Ss = reinterpret_cast<uint32_t*>(smem);

    const int tid = threadIdx.x;
    const int lane = tid & 31, wid = tid >> 5;
    const int wm = wid & 3, wn = wid >> 2;
    const int t = lane & 3, g = lane >> 2;
    const int bm = blockIdx.y * 128;
    const int bn = blockIdx.x * 128;

    const int arow = tid >> 3, ac4 = tid & 7;
    const int brow = tid >> 5, bc4 = tid & 31;

    float acc[2][8][4];
    #pragma unroll
    for (int i = 0; i < 2; i++)
        #pragma unroll
        for (int j = 0; j < 8; j++)
            #pragma unroll
            for (int e = 0; e < 4; e++) acc[i][j][e] = 0.f;

    const int nk = Kk >> 5;

    auto load_stage = [&](int stage, int kt){
        uint32_t abase = sbase + (stage * A_STG) * 4;
        #pragma unroll
        for (int q = 0; q < 4; q++){
            int row = q * 32 + arow;
            cp16(abase + (row * AST + ac4 * 4) * 4,
                 &A[(size_t)(bm + row) * Kk + kt + ac4 * 4]);
        }
        uint32_t bbase = sbase + (2 * A_STG + stage * B_STG) * 4;
        #pragma unroll
        for (int q = 0; q < 4; q++){
            int row = q * 8 + brow;
            cp16(bbase + (row * BST + bc4 * 4) * 4,
                 &Bm[(size_t)(kt + row) * ldB + bn + bc4 * 4]);
        }
    };

    load_stage(0, 0);
    asm volatile("cp.async.commit_group;");

    for (int i = 0; i < nk; i++){
        if (i + 1 < nk) load_stage((i + 1) & 1, (i + 1) << 5);
        asm volatile("cp.async.commit_group;");
        asm volatile("cp.async.wait_group 1;");
        __syncthreads();

        const uint32_t* Ab = Ss + (i & 1) * A_STG;
        const uint32_t* Bb = Ss + 2 * A_STG + (i & 1) * B_STG;
        #pragma unroll
        for (int ks = 0; ks < 4; ks++){
            int k0 = ks * 8 + t, k1 = k0 + 4;
            uint32_t afr[2][4];
            #pragma unroll
            for (int mt = 0; mt < 2; mt++){
                int mr = wm * 32 + mt * 16 + g;
                afr[mt][0] = Ab[mr * AST + k0];
                afr[mt][1] = Ab[(mr + 8) * AST + k0];
                afr[mt][2] = Ab[mr * AST + k1];
                afr[mt][3] = Ab[(mr + 8) * AST + k1];
            }
            uint32_t bfr[8][2];
            #pragma unroll
            for (int nt = 0; nt < 8; nt++){
                int nc = wn * 64 + nt * 8 + g;
                bfr[nt][0] = Bb[k0 * BST + nc];
                bfr[nt][1] = Bb[k1 * BST + nc];
            }
            #pragma unroll
            for (int mt = 0; mt < 2; mt++)
                #pragma unroll
                for (int nt = 0; nt < 8; nt++)
                    mma_tf32(acc[mt][nt], afr[mt], bfr[nt]);
        }
        __syncthreads();
    }

    #pragma unroll
    for (int mt = 0; mt < 2; mt++){
        #pragma unroll
        for (int nt = 0; nt < 8; nt++){
            int r0 = bm + wm * 32 + mt * 16 + g;
            int c0 = bn + wn * 64 + nt * 8 + 2 * t;
            #pragma unroll
            for (int h = 0; h < 2; h++){
                int r = r0 + h * 8;
                float v0 = acc[mt][nt][h * 2 + 0];
                float v1 = acc[mt][nt][h * 2 + 1];
                if (EPI == 1){
                    if (c0 < 256)
                        *reinterpret_cast<float2*>(&Cmat[(size_t)r * 256 + c0]) =
                            make_float2(v0, v1);
                    else
                        *reinterpret_cast<float2*>(&out2[(size_t)r * 256 + (c0 - 256)]) =
                            make_float2(silu_f(v0), silu_f(v1));
                } else if (EPI == 2){
                    v0 = gelu_f(v0 + bias[c0]);
                    v1 = gelu_f(v1 + bias[c0 + 1]);
                    *reinterpret_cast<float2*>(&Cmat[(size_t)r * Nn + c0]) =
                        make_float2(v0, v1);
                } else if (EPI == 3){
                    if (bias){ v0 += bias[c0]; v1 += bias[c0 + 1]; }
                    float2 rv = *reinterpret_cast<const float2*>(&res[(size_t)r * Nn + c0]);
                    *reinterpret_cast<float2*>(&Cmat[(size_t)r * Nn + c0]) =
                        make_float2(v0 + rv.x, v1 + rv.y);
                } else {
                    if (c0 < Nn)
                        *reinterpret_cast<float2*>(&Cmat[(size_t)r * Nn + c0]) =
                            make_float2(v0, v1);
                }
            }
        }
    }
}

// -------------------- depthwise 3x3 conv + bias + SiLU (float4 channels) --------------------
__global__ void __launch_bounds__(256) conv_dw(const float* __restrict__ wc,
                                               const float* __restrict__ bc){
    int idx = blockIdx.x * 256 + threadIdx.x;    // BL*64 lanes
    int d4 = idx & 63;                           // float4 channel group
    int pix = idx >> 6;
    int b = pix >> 12;
    int l = pix & (LL - 1);
    int h = l >> 6;
    int w = l & 63;
    int d = d4 * 4;

    float4 acc = *reinterpret_cast<const float4*>(&bc[d]);
    #pragma unroll
    for (int dy = -1; dy <= 1; dy++){
        int hh = h + dy;
        if (hh < 0 || hh >= HH) continue;
        const float* rowp = &g_x1[((size_t)(b * LL + hh * WW)) * DI + d];
        #pragma unroll
        for (int dx = -1; dx <= 1; dx++){
            int w2 = w + dx;
            if (w2 < 0 || w2 >= WW) continue;
            float4 v = *reinterpret_cast<const float4*>(&rowp[(size_t)w2 * DI]);
            int j = (dy + 1) * 3 + (dx + 1);
            acc.x = fmaf(wc[(d + 0) * 9 + j], v.x, acc.x);
            acc.y = fmaf(wc[(d + 1) * 9 + j], v.y, acc.y);
            acc.z = fmaf(wc[(d + 2) * 9 + j], v.z, acc.z);
            acc.w = fmaf(wc[(d + 3) * 9 + j], v.w, acc.w);
        }
    }
    acc.x = silu_f(acc.x); acc.y = silu_f(acc.y);
    acc.z = silu_f(acc.z); acc.w = silu_f(acc.w);
    *reinterpret_cast<float4*>(&g_xc[(size_t)pix * DI + d]) = acc;
}

__global__ void zero_y(){
    size_t i = (size_t)blockIdx.x * 256 + threadIdx.x;
    g_y[i] = 0.f;
}

// -------------------- selective scan: pass 1 (chunk-local) --------------------
__global__ void __launch_bounds__(256) scan_pass1(
    const float* __restrict__ dtw, const float* __restrict__ dtb,
    const float* __restrict__ alog)
{
    int bk = blockIdx.x;
    int chunk = blockIdx.y;
    int b = bk >> 2, k = bk & 3;
    int d = threadIdx.x;
    __shared__ __align__(16) float tile[CS * 40];
    int T0 = chunk * CS;
    for (int i = d; i < CS * 40; i += 256){
        int t = i / 40, c = i - t * 40;
        int p = pmap(k, T0 + t);
        tile[i] = g_xd[(size_t)(b * LL + p) * 160 + k * 40 + c];
    }
    __syncthreads();

    float dw[RR];
    #pragma unroll
    for (int r = 0; r < RR; r++) dw[r] = dtw[(size_t)(k * DI + d) * RR + r];
    float db = dtb[k * DI + d];
    float Av[NS];
    #pragma unroll
    for (int n = 0; n < NS; n++) Av[n] = -__expf(alog[(size_t)(k * DI + d) * NS + n]);
    float A0 = Av[0];
    bool fast = true;
    #pragma unroll
    for (int n = 0; n < NS; n++){
        float e = Av[n] - (float)(n + 1) * A0;
        if (fabsf(e) > 1e-5f * fabsf(Av[n]) + 1e-12f) fast = false;
    }
    float dsum = 0.f;
    size_t base = ((size_t)(bk * NCH + chunk) * NS) * DI + d;

    if (fast){
        uint64_t hv[8];
        #pragma unroll
        for (int i = 0; i < 8; i++) hv[i] = pk2(0.f, 0.f);
        for (int t = 0; t < CS; t++){
            int p = pmap(k, T0 + t);
            float xt = g_xc[(size_t)(b * LL + p) * DI + d];
            const float* tr = &tile[t * 40];
            float dp = db;
            #pragma unroll
            for (int r = 0; r < RR; r++) dp = fmaf(dw[r], tr[r], dp);
            float delta = softplus_f(dp);
            dsum += delta;
            float du = delta * xt;
            float gg = __expf(delta * A0);
            float g2 = gg * gg;
            uint64_t g2v = pk2(g2, g2);
            uint64_t a = pk2(gg, g2);
            uint64_t duv = pk2(du, du);
            #pragma unroll
            for (int i = 0; i < 8; i++){
                float2 Bp = *reinterpret_cast<const float2*>(&tr[8 + 2 * i]);
                uint64_t t0 = mul2(duv, pk2(Bp.x, Bp.y));
                hv[i] = fma2(a, hv[i], t0);
                if (i < 7) a = mul2(a, g2v);
            }
        }
        #pragma unroll
        for (int i = 0; i < 8; i++){
            float lo, hi;
            upk2(lo, hi, hv[i]);
            g_S[base + (size_t)(2 * i) * DI] = lo;
            g_S[base + (size_t)(2 * i + 1) * DI] = hi;
        }
    } else {
        float S[NS];
        #pragma unroll
        for (int n = 0; n < NS; n++) S[n] = 0.f;
        for (int t = 0; t < CS; t++){
            int p = pmap(k, T0 + t);
            float xt = g_xc[(size_t)(b * LL + p) * DI + d];
            const float* tr = &tile[t * 40];
            float dp = db;
            #pragma unroll
            for (int r = 0; r < RR; r++) dp = fmaf(dw[r], tr[r], dp);
            float delta = softplus_f(dp);
            dsum += delta;
            float du = delta * xt;
            #pragma unroll
            for (int n = 0; n < NS; n++){
                float a = __expf(delta * Av[n]);
                S[n] = fmaf(a, S[n], du * tr[8 + n]);
            }
        }
        #pragma unroll
        for (int n = 0; n < NS; n++) g_S[base + (size_t)n * DI] = S[n];
    }
    #pragma unroll
    for (int n = 0; n < NS; n++)
        g_P[base + (size_t)n * DI] = __expf(dsum * Av[n]);
}

// -------------------- scan pass 2: carry across chunks --------------------
__global__ void scan_pass2(){
    int id = blockIdx.x * 256 + threadIdx.x;
    int d  = id & 255;
    int n  = (id >> 8) & 15;
    int bk = id >> 12;
    float Hc = 0.f;
    size_t stride = (size_t)NS * DI;
    size_t base = ((size_t)bk * NCH * NS + n) * DI + d;
    for (int c = 0; c < NCH; c++){
        size_t a = base + (size_t)c * stride;
        float Pv = g_P[a];
        float Sv = g_S[a];
        g_S[a] = Hc;
        Hc = fmaf(Pv, Hc, Sv);
    }
}

// -------------------- scan pass 3: replay + y + merge (atomic) --------------------
__global__ void __launch_bounds__(256) scan_pass3(
    const float* __restrict__ dtw, const float* __restrict__ dtb,
    const float* __restrict__ alog, const float* __restrict__ Dsv)
{
    int bk = blockIdx.x;
    int chunk = blockIdx.y;
    int b = bk >> 2, k = bk & 3;
    int d = threadIdx.x;
    __shared__ __align__(16) float tile[CS * 40];
    int T0 = chunk * CS;
    for (int i = d; i < CS * 40; i += 256){
        int t = i / 40, c = i - t * 40;
        int p = pmap(k, T0 + t);
        tile[i] = g_xd[(size_t)(b * LL + p) * 160 + k * 40 + c];
    }
    __syncthreads();

    float dw[RR];
    #pragma unroll
    for (int r = 0; r < RR; r++) dw[r] = dtw[(size_t)(k * DI + d) * RR + r];
    float db = dtb[k * DI + d];
    float Dk = Dsv[k * DI + d];
    float Av[NS];
    #pragma unroll
    for (int n = 0; n < NS; n++) Av[n] = -__expf(alog[(size_t)(k * DI + d) * NS + n]);
    float A0 = Av[0];
    bool fast = true;
    #pragma unroll
    for (int n = 0; n < NS; n++){
        float e = Av[n] - (float)(n + 1) * A0;
        if (fabsf(e) > 1e-5f * fabsf(Av[n]) + 1e-12f) fast = false;
    }
    size_t base = ((size_t)(bk * NCH + chunk) * NS) * DI + d;

    if (fast){
        uint64_t hv[8];
        #pragma unroll
        for (int i = 0; i < 8; i++)
            hv[i] = pk2(g_S[base + (size_t)(2 * i) * DI],
                        g_S[base + (size_t)(2 * i + 1) * DI]);
        for (int t = 0; t < CS; t++){
            int p = pmap(k, T0 + t);
            size_t pidx = (size_t)(b * LL + p) * DI + d;
            float xt = g_xc[pidx];
            const float* tr = &tile[t * 40];
            float dp = db;
            #pragma unroll
            for (int r = 0; r < RR; r++) dp = fmaf(dw[r], tr[r], dp);
            float delta = softplus_f(dp);
            float du = delta * xt;
            float gg = __expf(delta * A0);
            float g2 = gg * gg;
            uint64_t g2v = pk2(g2, g2);
            uint64_t a = pk2(gg, g2);
            uint64_t duv = pk2(du, du);
            uint64_t yv = pk2(0.f, 0.f);
            #pragma unroll
            for (int i = 0; i < 8; i++){
                float2 Bp = *reinterpret_cast<const float2*>(&tr[8 + 2 * i]);
                float2 Cp = *reinterpret_cast<const float2*>(&tr[24 + 2 * i]);
                uint64_t t0 = mul2(duv, pk2(Bp.x, Bp.y));
                hv[i] = fma2(a, hv[i], t0);
                yv = fma2(hv[i], pk2(Cp.x, Cp.y), yv);
                if (i < 7) a = mul2(a, g2v);
            }
            float ylo, yhi;
            upk2(ylo, yhi, yv);
            float y = ylo + yhi;
            y = fmaf(Dk, xt, y);
            atomicAdd(&g_y[pidx], y);
        }
    } else {
        float h[NS];
        #pragma unroll
        for (int n = 0; n < NS; n++) h[n] = g_S[base + (size_t)n * DI];
        for (int t = 0; t < CS; t++){
            int p = pmap(k, T0 + t);
            size_t pidx = (size_t)(b * LL + p) * DI + d;
            float xt = g_xc[pidx];
            const float* tr = &tile[t * 40];
            float dp = db;
            #pragma unroll
            for (int r = 0; r < RR; r++) dp = fmaf(dw[r], tr[r], dp);
            float delta = softplus_f(dp);
            float du = delta * xt;
            float y = 0.f;
            #pragma unroll
            for (int n = 0; n < NS; n++){
                float a = __expf(delta * Av[n]);
                h[n] = fmaf(a, h[n], du * tr[8 + n]);
                y = fmaf(h[n], tr[24 + n], y);
            }
            y = fmaf(Dk, xt, y);
            atomicAdd(&g_y[pidx], y);
        }
    }
}

// -------------------- out-norm (LN over DI) * silu(z) --------------------
__global__ void onorm_mul(const float* __restrict__ onw, const float* __restrict__ onb){
    int row = blockIdx.x;
    int d = threadIdx.x;
    float v = g_y[(size_t)row * DI + d];
    float s1 = v, s2 = v * v;
    #pragma unroll
    for (int o = 16; o; o >>= 1){
        s1 += __shfl_xor_sync(0xffffffffu, s1, o);
        s2 += __shfl_xor_sync(0xffffffffu, s2, o);
    }
    __shared__ float r1[8], r2[8];
    int w = d >> 5;
    if ((d & 31) == 0){ r1[w] = s1; r2[w] = s2; }
    __syncthreads();
    float a = 0.f, bsum = 0.f;
    #pragma unroll
    for (int i = 0; i < 8; i++){ a += r1[i]; bsum += r2[i]; }
    float mu = a / DI;
    float var = bsum / DI - mu * mu;
    float rs = rsqrtf(var + 1e-5f);
    float o = (v - mu) * rs * onw[d] + onb[d];
    g_yn[(size_t)row * DI + d] = o * g_sz[(size_t)row * DI + d];
}

// -------------------- host launch --------------------
extern "C" void kernel_launch(void* const* d_in, const int* in_sizes, int n_in,
                              void* d_out, int out_size)
{
    (void)in_sizes; (void)n_in; (void)out_size;
    const float* input     = (const float*)d_in[0];
    const float* ln1_w     = (const float*)d_in[1];
    const float* ln1_b     = (const float*)d_in[2];
    const float* in_proj_w = (const float*)d_in[3];
    const float* conv_w    = (const float*)d_in[4];
    const float* conv_b    = (const float*)d_in[5];
    const float* x_proj_w  = (const float*)d_in[6];
    const float* dt_w      = (const float*)d_in[7];
    const float* dt_b      = (const float*)d_in[8];
    const float* A_log     = (const float*)d_in[9];
    const float* Ds        = (const float*)d_in[10];
    const float* onorm_w   = (const float*)d_in[11];
    const float* onorm_b   = (const float*)d_in[12];
    const float* out_proj_w= (const float*)d_in[13];
    const float* ln2_w     = (const float*)d_in[14];
    const float* ln2_b     = (const float*)d_in[15];
    const float* fc1_w     = (const float*)d_in[16];
    const float* fc1_b     = (const float*)d_in[17];
    const float* fc2_w     = (const float*)d_in[18];
    const float* fc2_b     = (const float*)d_in[19];

    float *px1, *psz, *pxc, *pxd, *pyn, *pxmid, *ph, *pxn1, *pxn2, *pxpw;
    cudaGetSymbolAddress((void**)&px1,  g_x1);
    cudaGetSymbolAddress((void**)&psz,  g_sz);
    cudaGetSymbolAddress((void**)&pxc,  g_xc);
    cudaGetSymbolAddress((void**)&pxd,  g_xd);
    cudaGetSymbolAddress((void**)&pyn,  g_yn);
    cudaGetSymbolAddress((void**)&pxmid,g_xmid);
    cudaGetSymbolAddress((void**)&ph,   g_hbuf);
    cudaGetSymbolAddress((void**)&pxn1, g_xn1);
    cudaGetSymbolAddress((void**)&pxn2, g_xn2);
    cudaGetSymbolAddress((void**)&pxpw, g_xpw);

    static bool attr_done = false;
    if (!attr_done){
        cudaFuncSetAttribute(gemm_tc<0>, cudaFuncAttributeMaxDynamicSharedMemorySize, GEMM_SMEM);
        cudaFuncSetAttribute(gemm_tc<1>, cudaFuncAttributeMaxDynamicSharedMemorySize, GEMM_SMEM);
        cudaFuncSetAttribute(gemm_tc<2>, cudaFuncAttributeMaxDynamicSharedMemorySize, GEMM_SMEM);
        cudaFuncSetAttribute(gemm_tc<3>, cudaFuncAttributeMaxDynamicSharedMemorySize, GEMM_SMEM);
        attr_done = true;
    }

    // 0. transpose x_proj weights (tiny)
    xpw_transpose<<<256, 256>>>(x_proj_w);

    // 1. LN1 -> in_proj GEMM, split x_/silu(z)
    ln_norm<<<BL, 128>>>(input, pxn1, ln1_w, ln1_b);
    gemm_tc<1><<<dim3(4, 128), 256, GEMM_SMEM>>>(
        pxn1, in_proj_w, px1, BL, 512, 128, 512, nullptr, nullptr, psz);

    // 2. depthwise conv + bias + SiLU
    conv_dw<<<BL / 4, 256>>>(conv_w, conv_b);

    // 3. x_proj: [BL,256]@[256,160] (B padded to 256 cols)
    gemm_tc<0><<<dim3(2, 128), 256, GEMM_SMEM>>>(
        pxc, pxpw, pxd, BL, 160, 256, 256, nullptr, nullptr, nullptr);

    // 4. selective scan (chunked) + merge
    zero_y<<<(BL * DI) / 256, 256>>>();
    scan_pass1<<<dim3(16, NCH), 256>>>(dt_w, dt_b, A_log);
    scan_pass2<<<256, 256>>>();
    scan_pass3<<<dim3(16, NCH), 256>>>(dt_w, dt_b, A_log, Ds);

    // 5. out-norm * silu(z), then out_proj + residual(input)
    onorm_mul<<<BL, 256>>>(onorm_w, onorm_b);
    gemm_tc<3><<<dim3(1, 128), 256, GEMM_SMEM>>>(
        pyn, out_proj_w, pxmid, BL, 128, 256, 128, nullptr, input, nullptr);

    // 6. MLP: LN2 -> fc1+GELU -> fc2 + residual
    ln_norm<<<BL, 128>>>(pxmid, pxn2, ln2_w, ln2_b);
    gemm_tc<2><<<dim3(4, 128), 256, GEMM_SMEM>>>(
        pxn2, fc1_w, ph, BL, 512, 128, 512, fc1_b, nullptr, nullptr);
    gemm_tc<3><<<dim3(1, 128), 256, GEMM_SMEM>>>(
        ph, fc2_w, (float*)d_out, BL, 128, 512, 128, fc2_b, pxmid, nullptr);
}

// round 5
// speedup vs baseline: 1.6435x; 1.0595x over previous
#include <cuda_runtime.h>
#include <math.h>
#include <stdint.h>

// Problem constants
#define BQ 4
#define HH 64
#define WW 64
#define CC 128
#define DI 256
#define NS 16
#define RR 8
#define LL 4096       // H*W
#define BL (BQ*LL)    // 16384 pixel-rows
#define CS 128        // scan chunk size
#define NCH (LL/CS)   // 32 chunks

// -------------------- device scratch (static, no allocs) --------------------
__device__ __align__(16) float g_x1[BL*DI];        // x_ (conv input)
__device__ __align__(16) float g_sz[BL*DI];        // silu(z)
__device__ __align__(16) float g_xc[BL*DI];        // conv+silu output
__device__ __align__(16) float g_xd[BL*160];       // x_proj output per pixel
__device__ __align__(16) float g_y [BL*DI];        // scan merged output (atomic accum)
__device__ __align__(16) float g_yn[BL*DI];        // onorm(y) * silu(z)
__device__ __align__(16) float g_xmid[BL*CC];      // after out_proj + residual
__device__ __align__(16) float g_hbuf[BL*4*CC];    // MLP hidden
__device__ __align__(16) float g_xn1[BL*CC];       // LN1(input)
__device__ __align__(16) float g_xn2[BL*CC];       // LN2(xmid)
__device__ __align__(16) float g_xpw[256*256];     // x_proj_w transposed+padded
__device__ __align__(16) float g_P[16*NCH*NS*DI];  // chunk decay products
__device__ __align__(16) float g_S[16*NCH*NS*DI];  // chunk states

// -------------------- small math helpers --------------------
__device__ __forceinline__ float silu_f(float x){ return x / (1.f + __expf(-x)); }
__device__ __forceinline__ float softplus_f(float x){
    return fmaxf(x, 0.f) + __logf(1.f + __expf(-fabsf(x)));
}
__device__ __forceinline__ float gelu_f(float x){
    return 0.5f * x * (1.f + erff(x * 0.70710678118654752f));
}
__device__ __forceinline__ void mma_tf32(float c[4], const uint32_t a[4], const uint32_t b[2]){
    asm volatile(
        "mma.sync.aligned.m16n8k8.row.col.f32.tf32.tf32.f32 "
        "{%0,%1,%2,%3},{%4,%5,%6,%7},{%8,%9},{%0,%1,%2,%3};"
        : "+f"(c[0]), "+f"(c[1]), "+f"(c[2]), "+f"(c[3])
        : "r"(a[0]), "r"(a[1]), "r"(a[2]), "r"(a[3]), "r"(b[0]), "r"(b[1]));
}
__device__ __forceinline__ void cp16(uint32_t dst, const void* src){
    asm volatile("cp.async.cg.shared.global [%0], [%1], 16;" :: "r"(dst), "l"(src));
}
// packed f32x2
__device__ __forceinline__ uint64_t pk2(float lo, float hi){
    uint64_t r; asm("mov.b64 %0, {%1,%2};" : "=l"(r) : "f"(lo), "f"(hi)); return r;
}
__device__ __forceinline__ void upk2(float& lo, float& hi, uint64_t v){
    asm("mov.b64 {%0,%1}, %2;" : "=f"(lo), "=f"(hi) : "l"(v));
}
__device__ __forceinline__ uint64_t mul2(uint64_t a, uint64_t b){
    uint64_t r; asm("mul.rn.f32x2 %0,%1,%2;" : "=l"(r) : "l"(a), "l"(b)); return r;
}
__device__ __forceinline__ uint64_t fma2(uint64_t a, uint64_t b, uint64_t c){
    uint64_t r; asm("fma.rn.f32x2 %0,%1,%2,%3;" : "=l"(r) : "l"(a), "l"(b), "l"(c)); return r;
}
// pixel index read/written by scan direction k at global step T
__device__ __forceinline__ int pmap(int k, int T){
    int t = (k & 2) ? (LL - 1 - T) : T;
    return (k & 1) ? ((t & 63) * 64 + (t >> 6)) : t;
}

// -------------------- LN (stats + write normalized rows) --------------------
__global__ void ln_norm(const float* __restrict__ x, float* __restrict__ xo,
                        const float* __restrict__ w, const float* __restrict__ b){
    int row = blockIdx.x;
    float v = x[(size_t)row * CC + threadIdx.x];
    float s1 = v, s2 = v * v;
    #pragma unroll
    for (int o = 16; o; o >>= 1){
        s1 += __shfl_xor_sync(0xffffffffu, s1, o);
        s2 += __shfl_xor_sync(0xffffffffu, s2, o);
    }
    __shared__ float r1[4], r2[4];
    int wi = threadIdx.x >> 5;
    if ((threadIdx.x & 31) == 0){ r1[wi] = s1; r2[wi] = s2; }
    __syncthreads();
    float a = 0.f, bb = 0.f;
    #pragma unroll
    for (int i = 0; i < 4; i++){ a += r1[i]; bb += r2[i]; }
    float mu = a / CC;
    float var = bb / CC - mu * mu;
    float rs = rsqrtf(var + 1e-5f);
    xo[(size_t)row * CC + threadIdx.x] =
        (v - mu) * rs * w[threadIdx.x] + b[threadIdx.x];
}

// -------------------- transpose + pad x_proj_w: [160][256] -> [256][256] --------------------
__global__ void xpw_transpose(const float* __restrict__ w){
    int d = blockIdx.x;
    int n = threadIdx.x;
    g_xpw[d * 256 + n] = (n < 160) ? w[(size_t)n * 256 + d] : 0.f;
}

// -------------------- TF32 tensor-core GEMM, cp.async 2-stage pipeline --------------------
#define AST 36
#define BST 136
#define A_STG (128*AST)
#define B_STG (32*BST)
#define GEMM_SMEM ((2*A_STG + 2*B_STG) * 4)

template<int EPI>
__global__ void __launch_bounds__(256, 2) gemm_tc(
    const float* __restrict__ A, const float* __restrict__ Bm, float* __restrict__ Cmat,
    int M, int Nn, int Kk, int ldB,
    const float* __restrict__ bias, const float* __restrict__ res, float* __restrict__ out2)
{
    extern __shared__ float smem[];
    uint32_t sbase;
    { void* p = smem; sbase = (uint32_t)__cvta_generic_to_shared(p); }
    uint32_t* Ss = reinterpret_cast<uint32_t*>(smem);

    const int tid = threadIdx.x;
    const int lane = tid & 31, wid = tid >> 5;
    const int wm = wid & 3, wn = wid >> 2;
    const int t = lane & 3, g = lane >> 2;
    const int bm = blockIdx.y * 128;
    const int bn = blockIdx.x * 128;

    const int arow = tid >> 3, ac4 = tid & 7;
    const int brow = tid >> 5, bc4 = tid & 31;

    float acc[2][8][4];
    #pragma unroll
    for (int i = 0; i < 2; i++)
        #pragma unroll
        for (int j = 0; j < 8; j++)
            #pragma unroll
            for (int e = 0; e < 4; e++) acc[i][j][e] = 0.f;

    const int nk = Kk >> 5;

    auto load_stage = [&](int stage, int kt){
        uint32_t abase = sbase + (stage * A_STG) * 4;
        #pragma unroll
        for (int q = 0; q < 4; q++){
            int row = q * 32 + arow;
            cp16(abase + (row * AST + ac4 * 4) * 4,
                 &A[(size_t)(bm + row) * Kk + kt + ac4 * 4]);
        }
        uint32_t bbase = sbase + (2 * A_STG + stage * B_STG) * 4;
        #pragma unroll
        for (int q = 0; q < 4; q++){
            int row = q * 8 + brow;
            cp16(bbase + (row * BST + bc4 * 4) * 4,
                 &Bm[(size_t)(kt + row) * ldB + bn + bc4 * 4]);
        }
    };

    load_stage(0, 0);
    asm volatile("cp.async.commit_group;");

    for (int i = 0; i < nk; i++){
        if (i + 1 < nk) load_stage((i + 1) & 1, (i + 1) << 5);
        asm volatile("cp.async.commit_group;");
        asm volatile("cp.async.wait_group 1;");
        __syncthreads();

        const uint32_t* Ab = Ss + (i & 1) * A_STG;
        const uint32_t* Bb = Ss + 2 * A_STG + (i & 1) * B_STG;
        #pragma unroll
        for (int ks = 0; ks < 4; ks++){
            int k0 = ks * 8 + t, k1 = k0 + 4;
            uint32_t afr[2][4];
            #pragma unroll
            for (int mt = 0; mt < 2; mt++){
                int mr = wm * 32 + mt * 16 + g;
                afr[mt][0] = Ab[mr * AST + k0];
                afr[mt][1] = Ab[(mr + 8) * AST + k0];
                afr[mt][2] = Ab[mr * AST + k1];
                afr[mt][3] = Ab[(mr + 8) * AST + k1];
            }
            uint32_t bfr[8][2];
            #pragma unroll
            for (int nt = 0; nt < 8; nt++){
                int nc = wn * 64 + nt * 8 + g;
                bfr[nt][0] = Bb[k0 * BST + nc];
                bfr[nt][1] = Bb[k1 * BST + nc];
            }
            #pragma unroll
            for (int mt = 0; mt < 2; mt++)
                #pragma unroll
                for (int nt = 0; nt < 8; nt++)
                    mma_tf32(acc[mt][nt], afr[mt], bfr[nt]);
        }
        __syncthreads();
    }

    #pragma unroll
    for (int mt = 0; mt < 2; mt++){
        #pragma unroll
        for (int nt = 0; nt < 8; nt++){
            int r0 = bm + wm * 32 + mt * 16 + g;
            int c0 = bn + wn * 64 + nt * 8 + 2 * t;
            #pragma unroll
            for (int h = 0; h < 2; h++){
                int r = r0 + h * 8;
                float v0 = acc[mt][nt][h * 2 + 0];
                float v1 = acc[mt][nt][h * 2 + 1];
                if (EPI == 1){
                    if (c0 < 256)
                        *reinterpret_cast<float2*>(&Cmat[(size_t)r * 256 + c0]) =
                            make_float2(v0, v1);
                    else
                        *reinterpret_cast<float2*>(&out2[(size_t)r * 256 + (c0 - 256)]) =
                            make_float2(silu_f(v0), silu_f(v1));
                } else if (EPI == 2){
                    v0 = gelu_f(v0 + bias[c0]);
                    v1 = gelu_f(v1 + bias[c0 + 1]);
                    *reinterpret_cast<float2*>(&Cmat[(size_t)r * Nn + c0]) =
                        make_float2(v0, v1);
                } else if (EPI == 3){
                    if (bias){ v0 += bias[c0]; v1 += bias[c0 + 1]; }
                    float2 rv = *reinterpret_cast<const float2*>(&res[(size_t)r * Nn + c0]);
                    *reinterpret_cast<float2*>(&Cmat[(size_t)r * Nn + c0]) =
                        make_float2(v0 + rv.x, v1 + rv.y);
                } else {
                    if (c0 < Nn)
                        *reinterpret_cast<float2*>(&Cmat[(size_t)r * Nn + c0]) =
                            make_float2(v0, v1);
                }
            }
        }
    }
}

// -------------------- depthwise 3x3 conv + bias + SiLU (smem tiled) --------------------
// Block: one H row x 64 pixels x 64 channels. smem holds rows h-1,h,h+1 with
// zero-padded w boundary. Each thread: 4 pixels x 4 channels via LDS.128.
#define CPG 64
#define CONV_SMEM (3*66*CPG*4)
__global__ void __launch_bounds__(256) conv_dw(const float* __restrict__ wc,
                                               const float* __restrict__ bc){
    extern __shared__ float cs[];   // [3][66][CPG]
    const int c0 = blockIdx.x * CPG;
    const int h  = blockIdx.y;
    const int b  = blockIdx.z;
    const int tid = threadIdx.x;

    // zero boundary w-columns (index 0 and 65): 3 rows * 2 cols * 64 ch / 4 = 96 float4
    if (tid < 96){
        int r = tid / 32;
        int col = (tid >> 4) & 1;
        int c4 = tid & 15;
        *reinterpret_cast<float4*>(&cs[(r * 66 + col * 65) * CPG + c4 * 4]) =
            make_float4(0.f, 0.f, 0.f, 0.f);
    }
    // load 3 input rows (zero-fill out-of-range rows)
    #pragma unroll
    for (int r = 0; r < 3; r++){
        int hh = h + r - 1;
        if (hh >= 0 && hh < HH){
            const float* src = &g_x1[((size_t)(b * LL + hh * WW)) * DI + c0];
            #pragma unroll
            for (int q = 0; q < 4; q++){
                int idx = q * 256 + tid;   // 0..1023
                int w = idx >> 4, c4 = idx & 15;
                *reinterpret_cast<float4*>(&cs[(r * 66 + w + 1) * CPG + c4 * 4]) =
                    *reinterpret_cast<const float4*>(&src[(size_t)w * DI + c4 * 4]);
            }
        } else {
            #pragma unroll
            for (int q = 0; q < 4; q++){
                int idx = q * 256 + tid;
                int w = idx >> 4, c4 = idx & 15;
                *reinterpret_cast<float4*>(&cs[(r * 66 + w + 1) * CPG + c4 * 4]) =
                    make_float4(0.f, 0.f, 0.f, 0.f);
            }
        }
    }
    __syncthreads();

    const int cg = tid & 15;
    const int d = c0 + cg * 4;
    float wr[4][9];
    #pragma unroll
    for (int e = 0; e < 4; e++)
        #pragma unroll
        for (int j = 0; j < 9; j++) wr[e][j] = wc[(d + e) * 9 + j];
    const float4 bias = *reinterpret_cast<const float4*>(&bc[d]);

    #pragma unroll
    for (int it = 0; it < 4; it++){
        int w = it * 16 + (tid >> 4);
        float4 acc = bias;
        #pragma unroll
        for (int r = 0; r < 3; r++){
            #pragma unroll
            for (int dx = 0; dx < 3; dx++){
                float4 v = *reinterpret_cast<const float4*>(
                    &cs[(r * 66 + w + dx) * CPG + cg * 4]);
                int j = r * 3 + dx;
                acc.x = fmaf(wr[0][j], v.x, acc.x);
                acc.y = fmaf(wr[1][j], v.y, acc.y);
                acc.z = fmaf(wr[2][j], v.z, acc.z);
                acc.w = fmaf(wr[3][j], v.w, acc.w);
            }
        }
        acc.x = silu_f(acc.x); acc.y = silu_f(acc.y);
        acc.z = silu_f(acc.z); acc.w = silu_f(acc.w);
        *reinterpret_cast<float4*>(
            &g_xc[((size_t)(b * LL + h * WW + w)) * DI + d]) = acc;
    }
}

__global__ void zero_y(){
    size_t i = (size_t)blockIdx.x * 256 + threadIdx.x;
    g_y[i] = 0.f;
}

// -------------------- selective scan: pass 1 (chunk-local) --------------------
__global__ void __launch_bounds__(256) scan_pass1(
    const float* __restrict__ dtw, const float* __restrict__ dtb,
    const float* __restrict__ alog)
{
    int bk = blockIdx.x;
    int chunk = blockIdx.y;
    int b = bk >> 2, k = bk & 3;
    int d = threadIdx.x;
    __shared__ __align__(16) float tile[CS * 40];
    int T0 = chunk * CS;
    for (int i = d; i < CS * 40; i += 256){
        int t = i / 40, c = i - t * 40;
        int p = pmap(k, T0 + t);
        tile[i] = g_xd[(size_t)(b * LL + p) * 160 + k * 40 + c];
    }
    __syncthreads();

    float dw[RR];
    #pragma unroll
    for (int r = 0; r < RR; r++) dw[r] = dtw[(size_t)(k * DI + d) * RR + r];
    float db = dtb[k * DI + d];
    float Av[NS];
    #pragma unroll
    for (int n = 0; n < NS; n++) Av[n] = -__expf(alog[(size_t)(k * DI + d) * NS + n]);
    float A0 = Av[0];
    bool fast = true;
    #pragma unroll
    for (int n = 0; n < NS; n++){
        float e = Av[n] - (float)(n + 1) * A0;
        if (fabsf(e) > 1e-5f * fabsf(Av[n]) + 1e-12f) fast = false;
    }
    float dsum = 0.f;
    size_t base = ((size_t)(bk * NCH + chunk) * NS) * DI + d;

    if (fast){
        uint64_t hv[8];
        #pragma unroll
        for (int i = 0; i < 8; i++) hv[i] = pk2(0.f, 0.f);
        for (int t = 0; t < CS; t++){
            int p = pmap(k, T0 + t);
            float xt = g_xc[(size_t)(b * LL + p) * DI + d];
            const float* tr = &tile[t * 40];
            float dp = db;
            #pragma unroll
            for (int r = 0; r < RR; r++) dp = fmaf(dw[r], tr[r], dp);
            float delta = softplus_f(dp);
            dsum += delta;
            float du = delta * xt;
            float gg = __expf(delta * A0);
            float g2 = gg * gg;
            uint64_t g2v = pk2(g2, g2);
            uint64_t a = pk2(gg, g2);
            uint64_t duv = pk2(du, du);
            #pragma unroll
            for (int i = 0; i < 8; i++){
                float2 Bp = *reinterpret_cast<const float2*>(&tr[8 + 2 * i]);
                uint64_t t0 = mul2(duv, pk2(Bp.x, Bp.y));
                hv[i] = fma2(a, hv[i], t0);
                if (i < 7) a = mul2(a, g2v);
            }
        }
        #pragma unroll
        for (int i = 0; i < 8; i++){
            float lo, hi;
            upk2(lo, hi, hv[i]);
            g_S[base + (size_t)(2 * i) * DI] = lo;
            g_S[base + (size_t)(2 * i + 1) * DI] = hi;
        }
    } else {
        float S[NS];
        #pragma unroll
        for (int n = 0; n < NS; n++) S[n] = 0.f;
        for (int t = 0; t < CS; t++){
            int p = pmap(k, T0 + t);
            float xt = g_xc[(size_t)(b * LL + p) * DI + d];
            const float* tr = &tile[t * 40];
            float dp = db;
            #pragma unroll
            for (int r = 0; r < RR; r++) dp = fmaf(dw[r], tr[r], dp);
            float delta = softplus_f(dp);
            dsum += delta;
            float du = delta * xt;
            #pragma unroll
            for (int n = 0; n < NS; n++){
                float a = __expf(delta * Av[n]);
                S[n] = fmaf(a, S[n], du * tr[8 + n]);
            }
        }
        #pragma unroll
        for (int n = 0; n < NS; n++) g_S[base + (size_t)n * DI] = S[n];
    }
    #pragma unroll
    for (int n = 0; n < NS; n++)
        g_P[base + (size_t)n * DI] = __expf(dsum * Av[n]);
}

// -------------------- scan pass 2: carry across chunks --------------------
__global__ void scan_pass2(){
    int id = blockIdx.x * 256 + threadIdx.x;
    int d  = id & 255;
    int n  = (id >> 8) & 15;
    int bk = id >> 12;
    float Hc = 0.f;
    size_t stride = (size_t)NS * DI;
    size_t base = ((size_t)bk * NCH * NS + n) * DI + d;
    for (int c = 0; c < NCH; c++){
        size_t a = base + (size_t)c * stride;
        float Pv = g_P[a];
        float Sv = g_S[a];
        g_S[a] = Hc;
        Hc = fmaf(Pv, Hc, Sv);
    }
}

// -------------------- scan pass 3: replay + y + merge (atomic) --------------------
__global__ void __launch_bounds__(256) scan_pass3(
    const float* __restrict__ dtw, const float* __restrict__ dtb,
    const float* __restrict__ alog, const float* __restrict__ Dsv)
{
    int bk = blockIdx.x;
    int chunk = blockIdx.y;
    int b = bk >> 2, k = bk & 3;
    int d = threadIdx.x;
    __shared__ __align__(16) float tile[CS * 40];
    int T0 = chunk * CS;
    for (int i = d; i < CS * 40; i += 256){
        int t = i / 40, c = i - t * 40;
        int p = pmap(k, T0 + t);
        tile[i] = g_xd[(size_t)(b * LL + p) * 160 + k * 40 + c];
    }
    __syncthreads();

    float dw[RR];
    #pragma unroll
    for (int r = 0; r < RR; r++) dw[r] = dtw[(size_t)(k * DI + d) * RR + r];
    float db = dtb[k * DI + d];
    float Dk = Dsv[k * DI + d];
    float Av[NS];
    #pragma unroll
    for (int n = 0; n < NS; n++) Av[n] = -__expf(alog[(size_t)(k * DI + d) * NS + n]);
    float A0 = Av[0];
    bool fast = true;
    #pragma unroll
    for (int n = 0; n < NS; n++){
        float e = Av[n] - (float)(n + 1) * A0;
        if (fabsf(e) > 1e-5f * fabsf(Av[n]) + 1e-12f) fast = false;
    }
    size_t base = ((size_t)(bk * NCH + chunk) * NS) * DI + d;

    if (fast){
        uint64_t hv[8];
        #pragma unroll
        for (int i = 0; i < 8; i++)
            hv[i] = pk2(g_S[base + (size_t)(2 * i) * DI],
                        g_S[base + (size_t)(2 * i + 1) * DI]);
        for (int t = 0; t < CS; t++){
            int p = pmap(k, T0 + t);
            size_t pidx = (size_t)(b * LL + p) * DI + d;
            float xt = g_xc[pidx];
            const float* tr = &tile[t * 40];
            float dp = db;
            #pragma unroll
            for (int r = 0; r < RR; r++) dp = fmaf(dw[r], tr[r], dp);
            float delta = softplus_f(dp);
            float du = delta * xt;
            float gg = __expf(delta * A0);
            float g2 = gg * gg;
            uint64_t g2v = pk2(g2, g2);
            uint64_t a = pk2(gg, g2);
            uint64_t duv = pk2(du, du);
            uint64_t yv = pk2(0.f, 0.f);
            #pragma unroll
            for (int i = 0; i < 8; i++){
                float2 Bp = *reinterpret_cast<const float2*>(&tr[8 + 2 * i]);
                float2 Cp = *reinterpret_cast<const float2*>(&tr[24 + 2 * i]);
                uint64_t t0 = mul2(duv, pk2(Bp.x, Bp.y));
                hv[i] = fma2(a, hv[i], t0);
                yv = fma2(hv[i], pk2(Cp.x, Cp.y), yv);
                if (i < 7) a = mul2(a, g2v);
            }
            float ylo, yhi;
            upk2(ylo, yhi, yv);
            float y = ylo + yhi;
            y = fmaf(Dk, xt, y);
            atomicAdd(&g_y[pidx], y);
        }
    } else {
        float h[NS];
        #pragma unroll
        for (int n = 0; n < NS; n++) h[n] = g_S[base + (size_t)n * DI];
        for (int t = 0; t < CS; t++){
            int p = pmap(k, T0 + t);
            size_t pidx = (size_t)(b * LL + p) * DI + d;
            float xt = g_xc[pidx];
            const float* tr = &tile[t * 40];
            float dp = db;
            #pragma unroll
            for (int r = 0; r < RR; r++) dp = fmaf(dw[r], tr[r], dp);
            float delta = softplus_f(dp);
            float du = delta * xt;
            float y = 0.f;
            #pragma unroll
            for (int n = 0; n < NS; n++){
                float a = __expf(delta * Av[n]);
                h[n] = fmaf(a, h[n], du * tr[8 + n]);
                y = fmaf(h[n], tr[24 + n], y);
            }
            y = fmaf(Dk, xt, y);
            atomicAdd(&g_y[pidx], y);
        }
    }
}

// -------------------- out-norm (LN over DI) * silu(z) --------------------
__global__ void onorm_mul(const float* __restrict__ onw, const float* __restrict__ onb){
    int row = blockIdx.x;
    int d = threadIdx.x;
    float v = g_y[(size_t)row * DI + d];
    float s1 = v, s2 = v * v;
    #pragma unroll
    for (int o = 16; o; o >>= 1){
        s1 += __shfl_xor_sync(0xffffffffu, s1, o);
        s2 += __shfl_xor_sync(0xffffffffu, s2, o);
    }
    __shared__ float r1[8], r2[8];
    int w = d >> 5;
    if ((d & 31) == 0){ r1[w] = s1; r2[w] = s2; }
    __syncthreads();
    float a = 0.f, bsum = 0.f;
    #pragma unroll
    for (int i = 0; i < 8; i++){ a += r1[i]; bsum += r2[i]; }
    float mu = a / DI;
    float var = bsum / DI - mu * mu;
    float rs = rsqrtf(var + 1e-5f);
    float o = (v - mu) * rs * onw[d] + onb[d];
    g_yn[(size_t)row * DI + d] = o * g_sz[(size_t)row * DI + d];
}

// -------------------- host launch --------------------
extern "C" void kernel_launch(void* const* d_in, const int* in_sizes, int n_in,
                              void* d_out, int out_size)
{
    (void)in_sizes; (void)n_in; (void)out_size;
    const float* input     = (const float*)d_in[0];
    const float* ln1_w     = (const float*)d_in[1];
    const float* ln1_b     = (const float*)d_in[2];
    const float* in_proj_w = (const float*)d_in[3];
    const float* conv_w    = (const float*)d_in[4];
    const float* conv_b    = (const float*)d_in[5];
    const float* x_proj_w  = (const float*)d_in[6];
    const float* dt_w      = (const float*)d_in[7];
    const float* dt_b      = (const float*)d_in[8];
    const float* A_log     = (const float*)d_in[9];
    const float* Ds        = (const float*)d_in[10];
    const float* onorm_w   = (const float*)d_in[11];
    const float* onorm_b   = (const float*)d_in[12];
    const float* out_proj_w= (const float*)d_in[13];
    const float* ln2_w     = (const float*)d_in[14];
    const float* ln2_b     = (const float*)d_in[15];
    const float* fc1_w     = (const float*)d_in[16];
    const float* fc1_b     = (const float*)d_in[17];
    const float* fc2_w     = (const float*)d_in[18];
    const float* fc2_b     = (const float*)d_in[19];

    float *px1, *psz, *pxc, *pxd, *pyn, *pxmid, *ph, *pxn1, *pxn2, *pxpw;
    cudaGetSymbolAddress((void**)&px1,  g_x1);
    cudaGetSymbolAddress((void**)&psz,  g_sz);
    cudaGetSymbolAddress((void**)&pxc,  g_xc);
    cudaGetSymbolAddress((void**)&pxd,  g_xd);
    cudaGetSymbolAddress((void**)&pyn,  g_yn);
    cudaGetSymbolAddress((void**)&pxmid,g_xmid);
    cudaGetSymbolAddress((void**)&ph,   g_hbuf);
    cudaGetSymbolAddress((void**)&pxn1, g_xn1);
    cudaGetSymbolAddress((void**)&pxn2, g_xn2);
    cudaGetSymbolAddress((void**)&pxpw, g_xpw);

    static bool attr_done = false;
    if (!attr_done){
        cudaFuncSetAttribute(gemm_tc<0>, cudaFuncAttributeMaxDynamicSharedMemorySize, GEMM_SMEM);
        cudaFuncSetAttribute(gemm_tc<1>, cudaFuncAttributeMaxDynamicSharedMemorySize, GEMM_SMEM);
        cudaFuncSetAttribute(gemm_tc<2>, cudaFuncAttributeMaxDynamicSharedMemorySize, GEMM_SMEM);
        cudaFuncSetAttribute(gemm_tc<3>, cudaFuncAttributeMaxDynamicSharedMemorySize, GEMM_SMEM);
        cudaFuncSetAttribute(conv_dw,   cudaFuncAttributeMaxDynamicSharedMemorySize, CONV_SMEM);
        attr_done = true;
    }

    // 0. transpose x_proj weights (tiny)
    xpw_transpose<<<256, 256>>>(x_proj_w);

    // 1. LN1 -> in_proj GEMM, split x_/silu(z)
    ln_norm<<<BL, 128>>>(input, pxn1, ln1_w, ln1_b);
    gemm_tc<1><<<dim3(4, 128), 256, GEMM_SMEM>>>(
        pxn1, in_proj_w, px1, BL, 512, 128, 512, nullptr, nullptr, psz);

    // 2. depthwise conv + bias + SiLU (smem tiled)
    conv_dw<<<dim3(DI / CPG, HH, BQ), 256, CONV_SMEM>>>(conv_w, conv_b);

    // 3. x_proj: [BL,256]@[256,160] (B padded to 256 cols)
    gemm_tc<0><<<dim3(2, 128), 256, GEMM_SMEM>>>(
        pxc, pxpw, pxd, BL, 160, 256, 256, nullptr, nullptr, nullptr);

    // 4. selective scan (chunked) + merge
    zero_y<<<(BL * DI) / 256, 256>>>();
    scan_pass1<<<dim3(16, NCH), 256>>>(dt_w, dt_b, A_log);
    scan_pass2<<<256, 256>>>();
    scan_pass3<<<dim3(16, NCH), 256>>>(dt_w, dt_b, A_log, Ds);

    // 5. out-norm * silu(z), then out_proj + residual(input)
    onorm_mul<<<BL, 256>>>(onorm_w, onorm_b);
    gemm_tc<3><<<dim3(1, 128), 256, GEMM_SMEM>>>(
        pyn, out_proj_w, pxmid, BL, 128, 256, 128, nullptr, input, nullptr);

    // 6. MLP: LN2 -> fc1+GELU -> fc2 + residual
    ln_norm<<<BL, 128>>>(pxmid, pxn2, ln2_w, ln2_b);
    gemm_tc<2><<<dim3(4, 128), 256, GEMM_SMEM>>>(
        pxn2, fc1_w, ph, BL, 512, 128, 512, fc1_b, nullptr, nullptr);
    gemm_tc<3><<<dim3(1, 128), 256, GEMM_SMEM>>>(
        ph, fc2_w, (float*)d_out, BL, 128, 512, 128, fc2_b, pxmid, nullptr);
}

// round 6
// speedup vs baseline: 1.7359x; 1.0562x over previous
#include <cuda_runtime.h>
#include <math.h>
#include <stdint.h>

// Problem constants
#define BQ 4
#define HH 64
#define WW 64
#define CC 128
#define DI 256
#define NS 16
#define RR 8
#define LL 4096       // H*W
#define BL (BQ*LL)    // 16384 pixel-rows
#define CS 128        // scan chunk size
#define NCH (LL/CS)   // 32 chunks

// -------------------- device scratch (static, no allocs) --------------------
__device__ __align__(16) float g_x1[BL*DI];        // x_ (conv input)
__device__ __align__(16) float g_sz[BL*DI];        // silu(z)
__device__ __align__(16) float g_xc[BL*DI];        // conv+silu output
__device__ __align__(16) float g_xd[BL*160];       // x_proj output per pixel
__device__ __align__(16) float g_y [BL*DI];        // scan merged output (atomic accum)
__device__ __align__(16) float g_yn[BL*DI];        // onorm(y) * silu(z)
__device__ __align__(16) float g_xmid[BL*CC];      // after out_proj + residual
__device__ __align__(16) float g_hbuf[BL*4*CC];    // MLP hidden
__device__ __align__(16) float g_xn1[BL*CC];       // LN1(input)
__device__ __align__(16) float g_xn2[BL*CC];       // LN2(xmid)
__device__ __align__(16) float g_xpw[256*256];     // x_proj_w transposed+padded
__device__ __align__(16) float g_P[16*NCH*NS*DI];  // chunk decay products
__device__ __align__(16) float g_S[16*NCH*NS*DI];  // chunk states

// -------------------- small math helpers --------------------
__device__ __forceinline__ float silu_f(float x){ return x / (1.f + __expf(-x)); }
__device__ __forceinline__ float softplus_f(float x){
    return fmaxf(x, 0.f) + __logf(1.f + __expf(-fabsf(x)));
}
__device__ __forceinline__ float gelu_f(float x){
    return 0.5f * x * (1.f + erff(x * 0.70710678118654752f));
}
__device__ __forceinline__ void mma_tf32(float c[4], const uint32_t a[4], const uint32_t b[2]){
    asm volatile(
        "mma.sync.aligned.m16n8k8.row.col.f32.tf32.tf32.f32 "
        "{%0,%1,%2,%3},{%4,%5,%6,%7},{%8,%9},{%0,%1,%2,%3};"
        : "+f"(c[0]), "+f"(c[1]), "+f"(c[2]), "+f"(c[3])
        : "r"(a[0]), "r"(a[1]), "r"(a[2]), "r"(a[3]), "r"(b[0]), "r"(b[1]));
}
__device__ __forceinline__ void cp16(uint32_t dst, const void* src){
    asm volatile("cp.async.cg.shared.global [%0], [%1], 16;" :: "r"(dst), "l"(src));
}
// packed f32x2
__device__ __forceinline__ uint64_t pk2(float lo, float hi){
    uint64_t r; asm("mov.b64 %0, {%1,%2};" : "=l"(r) : "f"(lo), "f"(hi)); return r;
}
__device__ __forceinline__ void upk2(float& lo, float& hi, uint64_t v){
    asm("mov.b64 {%0,%1}, %2;" : "=f"(lo), "=f"(hi) : "l"(v));
}
__device__ __forceinline__ uint64_t mul2(uint64_t a, uint64_t b){
    uint64_t r; asm("mul.rn.f32x2 %0,%1,%2;" : "=l"(r) : "l"(a), "l"(b)); return r;
}
__device__ __forceinline__ uint64_t fma2(uint64_t a, uint64_t b, uint64_t c){
    uint64_t r; asm("fma.rn.f32x2 %0,%1,%2,%3;" : "=l"(r) : "l"(a), "l"(b), "l"(c)); return r;
}
// pixel index read/written by scan direction k at global step T
__device__ __forceinline__ int pmap(int k, int T){
    int t = (k & 2) ? (LL - 1 - T) : T;
    return (k & 1) ? ((t & 63) * 64 + (t >> 6)) : t;
}

// -------------------- LN (stats + write normalized rows) --------------------
__global__ void ln_norm(const float* __restrict__ x, float* __restrict__ xo,
                        const float* __restrict__ w, const float* __restrict__ b){
    int row = blockIdx.x;
    float v = x[(size_t)row * CC + threadIdx.x];
    float s1 = v, s2 = v * v;
    #pragma unroll
    for (int o = 16; o; o >>= 1){
        s1 += __shfl_xor_sync(0xffffffffu, s1, o);
        s2 += __shfl_xor_sync(0xffffffffu, s2, o);
    }
    __shared__ float r1[4], r2[4];
    int wi = threadIdx.x >> 5;
    if ((threadIdx.x & 31) == 0){ r1[wi] = s1; r2[wi] = s2; }
    __syncthreads();
    float a = 0.f, bb = 0.f;
    #pragma unroll
    for (int i = 0; i < 4; i++){ a += r1[i]; bb += r2[i]; }
    float mu = a / CC;
    float var = bb / CC - mu * mu;
    float rs = rsqrtf(var + 1e-5f);
    xo[(size_t)row * CC + threadIdx.x] =
        (v - mu) * rs * w[threadIdx.x] + b[threadIdx.x];
}

// -------------------- transpose + pad x_proj_w: [160][256] -> [256][256] --------------------
__global__ void xpw_transpose(const float* __restrict__ w){
    int d = blockIdx.x;
    int n = threadIdx.x;
    g_xpw[d * 256 + n] = (n < 160) ? w[(size_t)n * 256 + d] : 0.f;
}

// -------------------- TF32 tensor-core GEMM, cp.async 3-stage pipeline --------------------
#define AST 36
#define BST 136
#define A_STG (128*AST)
#define B_STG (32*BST)
#define STG (A_STG + B_STG)
#define GEMM_SMEM (3 * STG * 4)

// EPI: 0 plain(+Nguard) | 1 split x_/silu(z) | 2 bias+gelu | 3 bias?+residual
//      4 residual + fused LN (writes Cmat=raw, out2=LN(raw); lnw/lnb params)
template<int EPI>
__global__ void __launch_bounds__(256, 2) gemm_tc(
    const float* __restrict__ A, const float* __restrict__ Bm, float* __restrict__ Cmat,
    int M, int Nn, int Kk, int ldB,
    const float* __restrict__ bias, const float* __restrict__ res, float* __restrict__ out2,
    const float* __restrict__ lnw, const float* __restrict__ lnb)
{
    extern __shared__ float smem[];
    uint32_t sbase;
    { void* p = smem; sbase = (uint32_t)__cvta_generic_to_shared(p); }
    uint32_t* Ss = reinterpret_cast<uint32_t*>(smem);

    const int tid = threadIdx.x;
    const int lane = tid & 31, wid = tid >> 5;
    const int wm = wid & 3, wn = wid >> 2;
    const int t = lane & 3, g = lane >> 2;
    const int bm = blockIdx.y * 128;
    const int bn = blockIdx.x * 128;

    const int arow = tid >> 3, ac4 = tid & 7;
    const int brow = tid >> 5, bc4 = tid & 31;

    float acc[2][8][4];
    #pragma unroll
    for (int i = 0; i < 2; i++)
        #pragma unroll
        for (int j = 0; j < 8; j++)
            #pragma unroll
            for (int e = 0; e < 4; e++) acc[i][j][e] = 0.f;

    const int nk = Kk >> 5;

    auto load_stage = [&](int stage, int kt){
        uint32_t abase = sbase + (stage * STG) * 4;
        #pragma unroll
        for (int q = 0; q < 4; q++){
            int row = q * 32 + arow;
            cp16(abase + (row * AST + ac4 * 4) * 4,
                 &A[(size_t)(bm + row) * Kk + kt + ac4 * 4]);
        }
        uint32_t bbase = abase + A_STG * 4;
        #pragma unroll
        for (int q = 0; q < 4; q++){
            int row = q * 8 + brow;
            cp16(bbase + (row * BST + bc4 * 4) * 4,
                 &Bm[(size_t)(kt + row) * ldB + bn + bc4 * 4]);
        }
    };

    // prologue: stages 0 and 1
    load_stage(0, 0);
    asm volatile("cp.async.commit_group;");
    if (nk > 1) load_stage(1, 32);
    asm volatile("cp.async.commit_group;");

    int st = 0;
    for (int i = 0; i < nk; i++){
        asm volatile("cp.async.wait_group 1;");
        __syncthreads();

        const uint32_t* Ab = Ss + st * STG;
        const uint32_t* Bb = Ab + A_STG;
        // issue load for stage i+2 (its buffer was consumed at iter i-1;
        // the barrier above ordered that consumption)
        if (i + 2 < nk){
            int s2 = st + 2; if (s2 >= 3) s2 -= 3;
            load_stage(s2, (i + 2) << 5);
        }
        asm volatile("cp.async.commit_group;");

        #pragma unroll
        for (int ks = 0; ks < 4; ks++){
            int k0 = ks * 8 + t, k1 = k0 + 4;
            uint32_t afr[2][4];
            #pragma unroll
            for (int mt = 0; mt < 2; mt++){
                int mr = wm * 32 + mt * 16 + g;
                afr[mt][0] = Ab[mr * AST + k0];
                afr[mt][1] = Ab[(mr + 8) * AST + k0];
                afr[mt][2] = Ab[mr * AST + k1];
                afr[mt][3] = Ab[(mr + 8) * AST + k1];
            }
            uint32_t bfr[8][2];
            #pragma unroll
            for (int nt = 0; nt < 8; nt++){
                int nc = wn * 64 + nt * 8 + g;
                bfr[nt][0] = Bb[k0 * BST + nc];
                bfr[nt][1] = Bb[k1 * BST + nc];
            }
            #pragma unroll
            for (int mt = 0; mt < 2; mt++)
                #pragma unroll
                for (int nt = 0; nt < 8; nt++)
                    mma_tf32(acc[mt][nt], afr[mt], bfr[nt]);
        }
        if (++st == 3) st = 0;
    }

    if (EPI == 4){
        // residual add, stash full 128x128 tile in smem, per-row LN, dual write
        __syncthreads();
        float* sred = smem;   // stride 132
        #pragma unroll
        for (int mt = 0; mt < 2; mt++){
            #pragma unroll
            for (int nt = 0; nt < 8; nt++){
                int cl = wn * 64 + nt * 8 + 2 * t;
                #pragma unroll
                for (int h = 0; h < 2; h++){
                    int rl = wm * 32 + mt * 16 + g + h * 8;
                    float2 rv = *reinterpret_cast<const float2*>(
                        &res[(size_t)(bm + rl) * 128 + cl]);
                    sred[rl * 132 + cl]     = acc[mt][nt][h * 2 + 0] + rv.x;
                    sred[rl * 132 + cl + 1] = acc[mt][nt][h * 2 + 1] + rv.y;
                }
            }
        }
        __syncthreads();
        float4 wv = *reinterpret_cast<const float4*>(&lnw[lane * 4]);
        float4 bv = *reinterpret_cast<const float4*>(&lnb[lane * 4]);
        #pragma unroll
        for (int rr = 0; rr < 16; rr++){
            int rl = wid * 16 + rr;
            float4 v = *reinterpret_cast<const float4*>(&sred[rl * 132 + lane * 4]);
            float s1 = v.x + v.y + v.z + v.w;
            float s2 = fmaf(v.x, v.x, fmaf(v.y, v.y, fmaf(v.z, v.z, v.w * v.w)));
            #pragma unroll
            for (int o = 16; o; o >>= 1){
                s1 += __shfl_xor_sync(0xffffffffu, s1, o);
                s2 += __shfl_xor_sync(0xffffffffu, s2, o);
            }
            float mu = s1 * (1.f / 128.f);
            float var = s2 * (1.f / 128.f) - mu * mu;
            float rs = rsqrtf(var + 1e-5f);
            size_t go = (size_t)(bm + rl) * 128 + lane * 4;
            *reinterpret_cast<float4*>(&Cmat[go]) = v;
            float4 o4;
            o4.x = (v.x - mu) * rs * wv.x + bv.x;
            o4.y = (v.y - mu) * rs * wv.y + bv.y;
            o4.z = (v.z - mu) * rs * wv.z + bv.z;
            o4.w = (v.w - mu) * rs * wv.w + bv.w;
            *reinterpret_cast<float4*>(&out2[go]) = o4;
        }
        return;
    }

    #pragma unroll
    for (int mt = 0; mt < 2; mt++){
        #pragma unroll
        for (int nt = 0; nt < 8; nt++){
            int r0 = bm + wm * 32 + mt * 16 + g;
            int c0 = bn + wn * 64 + nt * 8 + 2 * t;
            #pragma unroll
            for (int h = 0; h < 2; h++){
                int r = r0 + h * 8;
                float v0 = acc[mt][nt][h * 2 + 0];
                float v1 = acc[mt][nt][h * 2 + 1];
                if (EPI == 1){
                    if (c0 < 256)
                        *reinterpret_cast<float2*>(&Cmat[(size_t)r * 256 + c0]) =
                            make_float2(v0, v1);
                    else
                        *reinterpret_cast<float2*>(&out2[(size_t)r * 256 + (c0 - 256)]) =
                            make_float2(silu_f(v0), silu_f(v1));
                } else if (EPI == 2){
                    v0 = gelu_f(v0 + bias[c0]);
                    v1 = gelu_f(v1 + bias[c0 + 1]);
                    *reinterpret_cast<float2*>(&Cmat[(size_t)r * Nn + c0]) =
                        make_float2(v0, v1);
                } else if (EPI == 3){
                    if (bias){ v0 += bias[c0]; v1 += bias[c0 + 1]; }
                    float2 rv = *reinterpret_cast<const float2*>(&res[(size_t)r * Nn + c0]);
                    *reinterpret_cast<float2*>(&Cmat[(size_t)r * Nn + c0]) =
                        make_float2(v0 + rv.x, v1 + rv.y);
                } else {
                    if (c0 < Nn)
                        *reinterpret_cast<float2*>(&Cmat[(size_t)r * Nn + c0]) =
                            make_float2(v0, v1);
                }
            }
        }
    }
}

// -------------------- depthwise 3x3 conv + bias + SiLU (smem tiled, CPG=32) --------------------
#define CPG 32
#define CONV_SMEM (3*66*CPG*4)
__global__ void __launch_bounds__(256) conv_dw(const float* __restrict__ wc,
                                               const float* __restrict__ bc){
    extern __shared__ float cs[];   // [3][66][CPG]
    const int c0 = blockIdx.x * CPG;
    const int h  = blockIdx.y;
    const int b  = blockIdx.z;
    const int tid = threadIdx.x;

    // zero boundary w-columns (0 and 65): 3 rows * 2 cols * 32 ch / 4 = 48 float4
    if (tid < 48){
        int r = tid / 16;
        int col = (tid >> 3) & 1;
        int c4 = tid & 7;
        *reinterpret_cast<float4*>(&cs[(r * 66 + col * 65) * CPG + c4 * 4]) =
            make_float4(0.f, 0.f, 0.f, 0.f);
    }
    #pragma unroll
    for (int r = 0; r < 3; r++){
        int hh = h + r - 1;
        if (hh >= 0 && hh < HH){
            const float* src = &g_x1[((size_t)(b * LL + hh * WW)) * DI + c0];
            #pragma unroll
            for (int q = 0; q < 2; q++){
                int idx = q * 256 + tid;   // 0..511
                int w = idx >> 3, c4 = idx & 7;
                *reinterpret_cast<float4*>(&cs[(r * 66 + w + 1) * CPG + c4 * 4]) =
                    *reinterpret_cast<const float4*>(&src[(size_t)w * DI + c4 * 4]);
            }
        } else {
            #pragma unroll
            for (int q = 0; q < 2; q++){
                int idx = q * 256 + tid;
                int w = idx >> 3, c4 = idx & 7;
                *reinterpret_cast<float4*>(&cs[(r * 66 + w + 1) * CPG + c4 * 4]) =
                    make_float4(0.f, 0.f, 0.f, 0.f);
            }
        }
    }
    __syncthreads();

    const int cg = tid & 7;
    const int d = c0 + cg * 4;
    float wr[4][9];
    #pragma unroll
    for (int e = 0; e < 4; e++)
        #pragma unroll
        for (int j = 0; j < 9; j++) wr[e][j] = wc[(d + e) * 9 + j];
    const float4 bias = *reinterpret_cast<const float4*>(&bc[d]);

    #pragma unroll
    for (int it = 0; it < 2; it++){
        int w = it * 32 + (tid >> 3);
        float4 acc = bias;
        #pragma unroll
        for (int r = 0; r < 3; r++){
            #pragma unroll
            for (int dx = 0; dx < 3; dx++){
                float4 v = *reinterpret_cast<const float4*>(
                    &cs[(r * 66 + w + dx) * CPG + cg * 4]);
                int j = r * 3 + dx;
                acc.x = fmaf(wr[0][j], v.x, acc.x);
                acc.y = fmaf(wr[1][j], v.y, acc.y);
                acc.z = fmaf(wr[2][j], v.z, acc.z);
                acc.w = fmaf(wr[3][j], v.w, acc.w);
            }
        }
        acc.x = silu_f(acc.x); acc.y = silu_f(acc.y);
        acc.z = silu_f(acc.z); acc.w = silu_f(acc.w);
        *reinterpret_cast<float4*>(
            &g_xc[((size_t)(b * LL + h * WW + w)) * DI + d]) = acc;
    }
}

// -------------------- selective scan: pass 1 (chunk-local) --------------------
__global__ void __launch_bounds__(256) scan_pass1(
    const float* __restrict__ dtw, const float* __restrict__ dtb,
    const float* __restrict__ alog)
{
    int bk = blockIdx.x;
    int chunk = blockIdx.y;
    int b = bk >> 2, k = bk & 3;
    int d = threadIdx.x;
    __shared__ __align__(16) float tile[CS * 40];
    int T0 = chunk * CS;
    for (int i = d; i < CS * 40; i += 256){
        int t = i / 40, c = i - t * 40;
        int p = pmap(k, T0 + t);
        tile[i] = g_xd[(size_t)(b * LL + p) * 160 + k * 40 + c];
    }
    __syncthreads();

    float dw[RR];
    #pragma unroll
    for (int r = 0; r < RR; r++) dw[r] = dtw[(size_t)(k * DI + d) * RR + r];
    float db = dtb[k * DI + d];
    float Av[NS];
    #pragma unroll
    for (int n = 0; n < NS; n++) Av[n] = -__expf(alog[(size_t)(k * DI + d) * NS + n]);
    float A0 = Av[0];
    bool fast = true;
    #pragma unroll
    for (int n = 0; n < NS; n++){
        float e = Av[n] - (float)(n + 1) * A0;
        if (fabsf(e) > 1e-5f * fabsf(Av[n]) + 1e-12f) fast = false;
    }
    float dsum = 0.f;
    size_t base = ((size_t)(bk * NCH + chunk) * NS) * DI + d;

    if (fast){
        uint64_t hv[8];
        #pragma unroll
        for (int i = 0; i < 8; i++) hv[i] = pk2(0.f, 0.f);
        for (int t = 0; t < CS; t++){
            int p = pmap(k, T0 + t);
            float xt = g_xc[(size_t)(b * LL + p) * DI + d];
            const float* tr = &tile[t * 40];
            float dp = db;
            #pragma unroll
            for (int r = 0; r < RR; r++) dp = fmaf(dw[r], tr[r], dp);
            float delta = softplus_f(dp);
            dsum += delta;
            float du = delta * xt;
            float gg = __expf(delta * A0);
            float g2 = gg * gg;
            uint64_t g2v = pk2(g2, g2);
            uint64_t a = pk2(gg, g2);
            uint64_t duv = pk2(du, du);
            #pragma unroll
            for (int i = 0; i < 8; i++){
                float2 Bp = *reinterpret_cast<const float2*>(&tr[8 + 2 * i]);
                uint64_t t0 = mul2(duv, pk2(Bp.x, Bp.y));
                hv[i] = fma2(a, hv[i], t0);
                if (i < 7) a = mul2(a, g2v);
            }
        }
        #pragma unroll
        for (int i = 0; i < 8; i++){
            float lo, hi;
            upk2(lo, hi, hv[i]);
            g_S[base + (size_t)(2 * i) * DI] = lo;
            g_S[base + (size_t)(2 * i + 1) * DI] = hi;
        }
    } else {
        float S[NS];
        #pragma unroll
        for (int n = 0; n < NS; n++) S[n] = 0.f;
        for (int t = 0; t < CS; t++){
            int p = pmap(k, T0 + t);
            float xt = g_xc[(size_t)(b * LL + p) * DI + d];
            const float* tr = &tile[t * 40];
            float dp = db;
            #pragma unroll
            for (int r = 0; r < RR; r++) dp = fmaf(dw[r], tr[r], dp);
            float delta = softplus_f(dp);
            dsum += delta;
            float du = delta * xt;
            #pragma unroll
            for (int n = 0; n < NS; n++){
                float a = __expf(delta * Av[n]);
                S[n] = fmaf(a, S[n], du * tr[8 + n]);
            }
        }
        #pragma unroll
        for (int n = 0; n < NS; n++) g_S[base + (size_t)n * DI] = S[n];
    }
    #pragma unroll
    for (int n = 0; n < NS; n++)
        g_P[base + (size_t)n * DI] = __expf(dsum * Av[n]);
}

// -------------------- scan pass 2: carry across chunks (+ zero g_y) --------------------
__global__ void scan_pass2(){
    int id = blockIdx.x * 256 + threadIdx.x;   // 65536 threads
    // zero g_y (BL*DI = 4,194,304 floats = 1,048,576 float4)
    float4* y4 = reinterpret_cast<float4*>(g_y);
    #pragma unroll
    for (int q = 0; q < 16; q++)
        y4[(size_t)q * 65536 + id] = make_float4(0.f, 0.f, 0.f, 0.f);

    int d  = id & 255;
    int n  = (id >> 8) & 15;
    int bk = id >> 12;
    float Hc = 0.f;
    size_t stride = (size_t)NS * DI;
    size_t base = ((size_t)bk * NCH * NS + n) * DI + d;
    #pragma unroll 4
    for (int c = 0; c < NCH; c++){
        size_t a = base + (size_t)c * stride;
        float Pv = g_P[a];
        float Sv = g_S[a];
        g_S[a] = Hc;
        Hc = fmaf(Pv, Hc, Sv);
    }
}

// -------------------- scan pass 3: replay + y + merge (atomic) --------------------
__global__ void __launch_bounds__(256) scan_pass3(
    const float* __restrict__ dtw, const float* __restrict__ dtb,
    const float* __restrict__ alog, const float* __restrict__ Dsv)
{
    int bk = blockIdx.x;
    int chunk = blockIdx.y;
    int b = bk >> 2, k = bk & 3;
    int d = threadIdx.x;
    __shared__ __align__(16) float tile[CS * 40];
    int T0 = chunk * CS;
    for (int i = d; i < CS * 40; i += 256){
        int t = i / 40, c = i - t * 40;
        int p = pmap(k, T0 + t);
        tile[i] = g_xd[(size_t)(b * LL + p) * 160 + k * 40 + c];
    }
    __syncthreads();

    float dw[RR];
    #pragma unroll
    for (int r = 0; r < RR; r++) dw[r] = dtw[(size_t)(k * DI + d) * RR + r];
    float db = dtb[k * DI + d];
    float Dk = Dsv[k * DI + d];
    float Av[NS];
    #pragma unroll
    for (int n = 0; n < NS; n++) Av[n] = -__expf(alog[(size_t)(k * DI + d) * NS + n]);
    float A0 = Av[0];
    bool fast = true;
    #pragma unroll
    for (int n = 0; n < NS; n++){
        float e = Av[n] - (float)(n + 1) * A0;
        if (fabsf(e) > 1e-5f * fabsf(Av[n]) + 1e-12f) fast = false;
    }
    size_t base = ((size_t)(bk * NCH + chunk) * NS) * DI + d;

    if (fast){
        uint64_t hv[8];
        #pragma unroll
        for (int i = 0; i < 8; i++)
            hv[i] = pk2(g_S[base + (size_t)(2 * i) * DI],
                        g_S[base + (size_t)(2 * i + 1) * DI]);
        for (int t = 0; t < CS; t++){
            int p = pmap(k, T0 + t);
            size_t pidx = (size_t)(b * LL + p) * DI + d;
            float xt = g_xc[pidx];
            const float* tr = &tile[t * 40];
            float dp = db;
            #pragma unroll
            for (int r = 0; r < RR; r++) dp = fmaf(dw[r], tr[r], dp);
            float delta = softplus_f(dp);
            float du = delta * xt;
            float gg = __expf(delta * A0);
            float g2 = gg * gg;
            uint64_t g2v = pk2(g2, g2);
            uint64_t a = pk2(gg, g2);
            uint64_t duv = pk2(du, du);
            uint64_t yv = pk2(0.f, 0.f);
            #pragma unroll
            for (int i = 0; i < 8; i++){
                float2 Bp = *reinterpret_cast<const float2*>(&tr[8 + 2 * i]);
                float2 Cp = *reinterpret_cast<const float2*>(&tr[24 + 2 * i]);
                uint64_t t0 = mul2(duv, pk2(Bp.x, Bp.y));
                hv[i] = fma2(a, hv[i], t0);
                yv = fma2(hv[i], pk2(Cp.x, Cp.y), yv);
                if (i < 7) a = mul2(a, g2v);
            }
            float ylo, yhi;
            upk2(ylo, yhi, yv);
            float y = ylo + yhi;
            y = fmaf(Dk, xt, y);
            atomicAdd(&g_y[pidx], y);
        }
    } else {
        float h[NS];
        #pragma unroll
        for (int n = 0; n < NS; n++) h[n] = g_S[base + (size_t)n * DI];
        for (int t = 0; t < CS; t++){
            int p = pmap(k, T0 + t);
            size_t pidx = (size_t)(b * LL + p) * DI + d;
            float xt = g_xc[pidx];
            const float* tr = &tile[t * 40];
            float dp = db;
            #pragma unroll
            for (int r = 0; r < RR; r++) dp = fmaf(dw[r], tr[r], dp);
            float delta = softplus_f(dp);
            float du = delta * xt;
            float y = 0.f;
            #pragma unroll
            for (int n = 0; n < NS; n++){
                float a = __expf(delta * Av[n]);
                h[n] = fmaf(a, h[n], du * tr[8 + n]);
                y = fmaf(h[n], tr[24 + n], y);
            }
            y = fmaf(Dk, xt, y);
            atomicAdd(&g_y[pidx], y);
        }
    }
}

// -------------------- out-norm (LN over DI) * silu(z) --------------------
__global__ void onorm_mul(const float* __restrict__ onw, const float* __restrict__ onb){
    int row = blockIdx.x;
    int d = threadIdx.x;
    float v = g_y[(size_t)row * DI + d];
    float s1 = v, s2 = v * v;
    #pragma unroll
    for (int o = 16; o; o >>= 1){
        s1 += __shfl_xor_sync(0xffffffffu, s1, o);
        s2 += __shfl_xor_sync(0xffffffffu, s2, o);
    }
    __shared__ float r1[8], r2[8];
    int w = d >> 5;
    if ((d & 31) == 0){ r1[w] = s1; r2[w] = s2; }
    __syncthreads();
    float a = 0.f, bsum = 0.f;
    #pragma unroll
    for (int i = 0; i < 8; i++){ a += r1[i]; bsum += r2[i]; }
    float mu = a / DI;
    float var = bsum / DI - mu * mu;
    float rs = rsqrtf(var + 1e-5f);
    float o = (v - mu) * rs * onw[d] + onb[d];
    g_yn[(size_t)row * DI + d] = o * g_sz[(size_t)row * DI + d];
}

// -------------------- host launch --------------------
extern "C" void kernel_launch(void* const* d_in, const int* in_sizes, int n_in,
                              void* d_out, int out_size)
{
    (void)in_sizes; (void)n_in; (void)out_size;
    const float* input     = (const float*)d_in[0];
    const float* ln1_w     = (const float*)d_in[1];
    const float* ln1_b     = (const float*)d_in[2];
    const float* in_proj_w = (const float*)d_in[3];
    const float* conv_w    = (const float*)d_in[4];
    const float* conv_b    = (const float*)d_in[5];
    const float* x_proj_w  = (const float*)d_in[6];
    const float* dt_w      = (const float*)d_in[7];
    const float* dt_b      = (const float*)d_in[8];
    const float* A_log     = (const float*)d_in[9];
    const float* Ds        = (const float*)d_in[10];
    const float* onorm_w   = (const float*)d_in[11];
    const float* onorm_b   = (const float*)d_in[12];
    const float* out_proj_w= (const float*)d_in[13];
    const float* ln2_w     = (const float*)d_in[14];
    const float* ln2_b     = (const float*)d_in[15];
    const float* fc1_w     = (const float*)d_in[16];
    const float* fc1_b     = (const float*)d_in[17];
    const float* fc2_w     = (const float*)d_in[18];
    const float* fc2_b     = (const float*)d_in[19];

    float *px1, *psz, *pxc, *pxd, *pyn, *pxmid, *ph, *pxn1, *pxn2, *pxpw;
    cudaGetSymbolAddress((void**)&px1,  g_x1);
    cudaGetSymbolAddress((void**)&psz,  g_sz);
    cudaGetSymbolAddress((void**)&pxc,  g_xc);
    cudaGetSymbolAddress((void**)&pxd,  g_xd);
    cudaGetSymbolAddress((void**)&pyn,  g_yn);
    cudaGetSymbolAddress((void**)&pxmid,g_xmid);
    cudaGetSymbolAddress((void**)&ph,   g_hbuf);
    cudaGetSymbolAddress((void**)&pxn1, g_xn1);
    cudaGetSymbolAddress((void**)&pxn2, g_xn2);
    cudaGetSymbolAddress((void**)&pxpw, g_xpw);

    static bool attr_done = false;
    if (!attr_done){
        cudaFuncSetAttribute(gemm_tc<0>, cudaFuncAttributeMaxDynamicSharedMemorySize, GEMM_SMEM);
        cudaFuncSetAttribute(gemm_tc<1>, cudaFuncAttributeMaxDynamicSharedMemorySize, GEMM_SMEM);
        cudaFuncSetAttribute(gemm_tc<2>, cudaFuncAttributeMaxDynamicSharedMemorySize, GEMM_SMEM);
        cudaFuncSetAttribute(gemm_tc<3>, cudaFuncAttributeMaxDynamicSharedMemorySize, GEMM_SMEM);
        cudaFuncSetAttribute(gemm_tc<4>, cudaFuncAttributeMaxDynamicSharedMemorySize, GEMM_SMEM);
        cudaFuncSetAttribute(conv_dw,   cudaFuncAttributeMaxDynamicSharedMemorySize, CONV_SMEM);
        attr_done = true;
    }

    // 0. transpose x_proj weights (tiny)
    xpw_transpose<<<256, 256>>>(x_proj_w);

    // 1. LN1 -> in_proj GEMM, split x_/silu(z)
    ln_norm<<<BL, 128>>>(input, pxn1, ln1_w, ln1_b);
    gemm_tc<1><<<dim3(4, 128), 256, GEMM_SMEM>>>(
        pxn1, in_proj_w, px1, BL, 512, 128, 512, nullptr, nullptr, psz,
        nullptr, nullptr);

    // 2. depthwise conv + bias + SiLU (smem tiled)
    conv_dw<<<dim3(DI / CPG, HH, BQ), 256, CONV_SMEM>>>(conv_w, conv_b);

    // 3. x_proj: [BL,256]@[256,160] (B padded to 256 cols)
    gemm_tc<0><<<dim3(2, 128), 256, GEMM_SMEM>>>(
        pxc, pxpw, pxd, BL, 160, 256, 256, nullptr, nullptr, nullptr,
        nullptr, nullptr);

    // 4. selective scan (chunked) + merge
    scan_pass1<<<dim3(16, NCH), 256>>>(dt_w, dt_b, A_log);
    scan_pass2<<<256, 256>>>();
    scan_pass3<<<dim3(16, NCH), 256>>>(dt_w, dt_b, A_log, Ds);

    // 5. out-norm * silu(z), then out_proj + residual(input) + fused LN2
    onorm_mul<<<BL, 256>>>(onorm_w, onorm_b);
    gemm_tc<4><<<dim3(1, 128), 256, GEMM_SMEM>>>(
        pyn, out_proj_w, pxmid, BL, 128, 256, 128, nullptr, input, pxn2,
        ln2_w, ln2_b);

    // 6. MLP: fc1+GELU -> fc2 + residual
    gemm_tc<2><<<dim3(4, 128), 256, GEMM_SMEM>>>(
        pxn2, fc1_w, ph, BL, 512, 128, 512, fc1_b, nullptr, nullptr,
        nullptr, nullptr);
    gemm_tc<3><<<dim3(1, 128), 256, GEMM_SMEM>>>(
        ph, fc2_w, (float*)d_out, BL, 128, 512, 128, fc2_b, pxmid, nullptr,
        nullptr, nullptr);
}